// round 11
// baseline (speedup 1.0000x reference)
#include <cuda_runtime.h>
#include <cuda_bf16.h>
#include <cstdint>

#define DE 273
#define EPSV 1e-12f
#define C2F 0.17677669529663688f  // 1/(4*sqrt(2))

// ----- scratch (static device allocations; no cudaMalloc allowed) -----
__device__ float gQKV[8192 * 1536];    // [m][0:256 Q | 256:512 K | 512:1536 V]
__device__ __nv_bfloat16 gHh[8192 * 1024];
__device__ __nv_bfloat16 gHl[8192 * 1024];
__device__ __nv_bfloat16 gWh[1536 * 1024];
__device__ __nv_bfloat16 gWl[1536 * 1024];
__device__ __nv_bfloat16 gWoh[1024 * 1024];
__device__ __nv_bfloat16 gWol[1024 * 1024];
__device__ __nv_bfloat16 gYh[8192 * 1024];
__device__ __nv_bfloat16 gYl[8192 * 1024];

// ============================================================================
// helpers (portable PTX only: cp.async / ldmatrix / mma.sync)
// ============================================================================
__device__ __forceinline__ uint32_t smem_u32(const void* p) {
    uint32_t a;
    asm("{ .reg .u64 t; cvta.to.shared.u64 t, %1; cvt.u32.u64 %0, t; }" : "=r"(a) : "l"(p));
    return a;
}
__device__ __forceinline__ void cpasync16(uint32_t dst, const void* src) {
    asm volatile("cp.async.cg.shared.global [%0], [%1], 16;" :: "r"(dst), "l"(src));
}
__device__ __forceinline__ void cpasync_commit() {
    asm volatile("cp.async.commit_group;" ::: "memory");
}
__device__ __forceinline__ void cpasync_wait_all() {
    asm volatile("cp.async.wait_group 0;" ::: "memory");
}
__device__ __forceinline__ void ldsm4(uint32_t* r, uint32_t addr) {
    asm volatile("ldmatrix.sync.aligned.m8n8.x4.shared.b16 {%0,%1,%2,%3}, [%4];"
        : "=r"(r[0]), "=r"(r[1]), "=r"(r[2]), "=r"(r[3]) : "r"(addr));
}
__device__ __forceinline__ void mma_bf16(float* d, const uint32_t* a, const uint32_t* b) {
    asm volatile(
        "mma.sync.aligned.m16n8k16.row.col.f32.bf16.bf16.f32 "
        "{%0,%1,%2,%3}, {%4,%5,%6,%7}, {%8,%9}, {%0,%1,%2,%3};"
        : "+f"(d[0]), "+f"(d[1]), "+f"(d[2]), "+f"(d[3])
        : "r"(a[0]), "r"(a[1]), "r"(a[2]), "r"(a[3]), "r"(b[0]), "r"(b[1]));
}
__device__ __forceinline__ uint32_t sw128(uint32_t bo) { return bo ^ ((bo >> 3) & 0x70); }
__device__ __forceinline__ uint32_t hipack(float x, float y) {
    __nv_bfloat162 h(__float2bfloat16(x), __float2bfloat16(y));
    return *(uint32_t*)&h;
}
__device__ __forceinline__ uint32_t lopack(float x, float y) {
    float xr = x - __bfloat162float(__float2bfloat16(x));
    float yr = y - __bfloat162float(__float2bfloat16(y));
    __nv_bfloat162 h(__float2bfloat16(xr), __float2bfloat16(yr));
    return *(uint32_t*)&h;
}

// ============================================================================
// fp32 -> (hi, lo) bf16 split conversions
// ============================================================================
__device__ __forceinline__ void cvt_body(const float* __restrict__ src,
                                         __nv_bfloat16* __restrict__ hi,
                                         __nv_bfloat16* __restrict__ lo, int i)
{
    float4 v = *(const float4*)(src + i);
    __nv_bfloat16 h0 = __float2bfloat16(v.x), h1 = __float2bfloat16(v.y);
    __nv_bfloat16 h2 = __float2bfloat16(v.z), h3 = __float2bfloat16(v.w);
    __nv_bfloat16 l0 = __float2bfloat16(v.x - __bfloat162float(h0));
    __nv_bfloat16 l1 = __float2bfloat16(v.y - __bfloat162float(h1));
    __nv_bfloat16 l2 = __float2bfloat16(v.z - __bfloat162float(h2));
    __nv_bfloat16 l3 = __float2bfloat16(v.w - __bfloat162float(h3));
    __nv_bfloat162* ph = (__nv_bfloat162*)(hi + i);
    __nv_bfloat162* pl = (__nv_bfloat162*)(lo + i);
    ph[0] = __nv_bfloat162(h0, h1); ph[1] = __nv_bfloat162(h2, h3);
    pl[0] = __nv_bfloat162(l0, l1); pl[1] = __nv_bfloat162(l2, l3);
}

__global__ void __launch_bounds__(256) cvt_hilo(
    const float* __restrict__ src, __nv_bfloat16* __restrict__ hi,
    __nv_bfloat16* __restrict__ lo)
{
    int i = (blockIdx.x * 256 + threadIdx.x) * 4;
    cvt_body(src, hi, lo, i);
}

// Wq (blocks 0..255) | Wk (256..511) | Wv (512..1535) -> contiguous hi/lo
__global__ void __launch_bounds__(256) cvt3_w(
    const float* __restrict__ Wq, const float* __restrict__ Wk,
    const float* __restrict__ Wv, __nv_bfloat16* __restrict__ hi,
    __nv_bfloat16* __restrict__ lo)
{
    int blk = blockIdx.x;
    int i = (blk * 256 + threadIdx.x) * 4;
    const float* src;
    if (blk < 256) src = Wq + i;
    else if (blk < 512) src = Wk + i - 256 * 1024;
    else src = Wv + i - 512 * 1024;
    cvt_body(src - i, hi, lo, i);
}

// ============================================================================
// split-bf16 HMMA GEMM (NT): unchanged from R7 (passing).
// ============================================================================
__global__ void __launch_bounds__(512, 1) gemm_mma(
    const __nv_bfloat16* __restrict__ Ah, const __nv_bfloat16* __restrict__ Al,
    const __nv_bfloat16* __restrict__ Bh, const __nv_bfloat16* __restrict__ Bl,
    float* __restrict__ C, int N, int K)
{
    extern __shared__ char smem[];
    const uint32_t sb = smem_u32(smem);
    const int tid = threadIdx.x, wid = tid >> 5, l = tid & 31;
    const int wm = wid & 3, wn = wid >> 2;
    const int bm = blockIdx.y * 128, bn = blockIdx.x * 128;

    const __nv_bfloat16* gp0[4] = {
        Ah + (size_t)bm * K, Al + (size_t)bm * K,
        Bh + (size_t)bn * K, Bl + (size_t)bn * K };

    const int NST = K >> 6;

    float acc[2][4][4];
#pragma unroll
    for (int mt = 0; mt < 2; ++mt)
#pragma unroll
        for (int nt = 0; nt < 4; ++nt)
#pragma unroll
            for (int c = 0; c < 4; ++c) acc[mt][nt][c] = 0.f;

    {
        const uint32_t sdst = sb;
#pragma unroll
        for (int t = 0; t < 4; ++t)
#pragma unroll
            for (int it = 0; it < 2; ++it) {
                int ch = tid + it * 512;
                int row = ch >> 3, cb = ch & 7;
                cpasync16(sdst + t * 16384 + sw128(row * 128 + cb * 16),
                          gp0[t] + (size_t)row * K + cb * 8);
            }
        cpasync_commit();
    }

    for (int s = 0; s < NST; ++s) {
        cpasync_wait_all();
        __syncthreads();
        if (s + 1 < NST) {
            const uint32_t sdst = sb + (uint32_t)((s + 1) & 1) * 65536u;
            const int k0 = (s + 1) * 64;
#pragma unroll
            for (int t = 0; t < 4; ++t)
#pragma unroll
                for (int it = 0; it < 2; ++it) {
                    int ch = tid + it * 512;
                    int row = ch >> 3, cb = ch & 7;
                    cpasync16(sdst + t * 16384 + sw128(row * 128 + cb * 16),
                              gp0[t] + (size_t)row * K + k0 + cb * 8);
                }
            cpasync_commit();
        }
        const uint32_t sc = sb + (uint32_t)(s & 1) * 65536u;
#pragma unroll
        for (int ks = 0; ks < 4; ++ks) {
            uint32_t ah[2][4], al[2][4];
#pragma unroll
            for (int mt = 0; mt < 2; ++mt) {
                uint32_t bo = (uint32_t)(wm * 32 + mt * 16 + (l & 15)) * 128
                            + ks * 32 + ((l >> 4) << 4);
                bo = sw128(bo);
                ldsm4(ah[mt], sc + bo);
                ldsm4(al[mt], sc + 16384 + bo);
            }
#pragma unroll
            for (int p = 0; p < 2; ++p) {
                uint32_t n = (uint32_t)(wn * 32 + p * 16 + (l & 7) + ((l >> 4) << 3));
                uint32_t bo = n * 128 + ks * 32 + (((l >> 3) & 1) << 4);
                bo = sw128(bo);
                uint32_t rb[4], rl[4];
                ldsm4(rb, sc + 32768 + bo);
                ldsm4(rl, sc + 49152 + bo);
                uint32_t b0[2] = {rb[0], rb[1]}, b1[2] = {rb[2], rb[3]};
                uint32_t c0[2] = {rl[0], rl[1]}, c1[2] = {rl[2], rl[3]};
#pragma unroll
                for (int mt = 0; mt < 2; ++mt) {
                    mma_bf16(acc[mt][2 * p],     ah[mt], b0);
                    mma_bf16(acc[mt][2 * p + 1], ah[mt], b1);
                    mma_bf16(acc[mt][2 * p],     ah[mt], c0);
                    mma_bf16(acc[mt][2 * p + 1], ah[mt], c1);
                    mma_bf16(acc[mt][2 * p],     al[mt], b0);
                    mma_bf16(acc[mt][2 * p + 1], al[mt], b1);
                }
            }
        }
        __syncthreads();
    }

    const int r0 = bm + wm * 32 + (l >> 2);
    const int c0 = bn + wn * 32 + 2 * (l & 3);
#pragma unroll
    for (int mt = 0; mt < 2; ++mt)
#pragma unroll
        for (int nt = 0; nt < 4; ++nt) {
            float* p0 = C + (size_t)(r0 + mt * 16) * N + c0 + nt * 8;
            float* p1 = C + (size_t)(r0 + mt * 16 + 8) * N + c0 + nt * 8;
            *(float2*)p0 = make_float2(acc[mt][nt][0], acc[mt][nt][1]);
            *(float2*)p1 = make_float2(acc[mt][nt][2], acc[mt][nt][3]);
        }
}

// ============================================================================
// attn_persist: one CTA per (b,h,e-half); S state (288x32 fp32) lives in SMEM
// for the whole 16-chunk causal scan.  512 threads, 16 warps = 8 m-slots x
// 2 n-groups (nh0: value cols e'0..31, nh1: den/z col).
// Per chunk:  dots MMA -> poly/mask in-fragment -> attn@[V^T|1] ->
//             qf@[S^T|z] (2 d-slices of 144) -> y out -> S += kf^T@[V^T|1].
// ============================================================================
#define LDQK 24    // 48B rows   (q/k 16-feat tiles)
#define LDV  136   // 272B rows  (V^T + ones tile, 40 rows)
#define LDB  152   // 304B rows  (S-slice B tile, 40 rows)
#define LDFQ 152   // 304B rows  (qf slice 128 x 144)
#define LDFK 136   // 272B rows  (kf slice 144 x 128)
#define DSL  144

__global__ void __launch_bounds__(512, 1) attn_persist()
{
    extern __shared__ char smraw[];
    float* sQ   = (float*)smraw;            // 128*17
    float* sK   = sQ + 2176;                // 128*17
    float* sDen = sK + 2176;                // 128
    float* sSf  = sDen + 128;               // 288*32
    float* sZf  = sSf + 9216;               // 288
    __nv_bfloat16* sQh = (__nv_bfloat16*)(sZf + 288);   // 128*24
    __nv_bfloat16* sQl = sQh + 3072;
    __nv_bfloat16* sKh = sQl + 3072;
    __nv_bfloat16* sKl = sKh + 3072;
    __nv_bfloat16* sVh = sKl + 3072;        // 40*136
    __nv_bfloat16* sVl = sVh + 5440;
    __nv_bfloat16* sBh = sVl + 5440;        // 40*152
    __nv_bfloat16* sBl = sBh + 6080;
    __nv_bfloat16* sFh = sBl + 6080;        // max(144*136, 128*152) = 19584
    __nv_bfloat16* sFl = sFh + 19584;

    const int bid = blockIdx.x;
    const int eh = bid & 1, bh = bid >> 1;
    const int b = bh >> 4, h = bh & 15;
    const int e0 = eh * 32;
    const int tid = threadIdx.x, wid = tid >> 5, l = tid & 31;
    const int wgrp = wid & 7, nh = wid >> 3;

    const uint32_t aQh = smem_u32(sQh), aQl = smem_u32(sQl);
    const uint32_t aKh = smem_u32(sKh), aKl = smem_u32(sKl);
    const uint32_t aVh = smem_u32(sVh), aVl = smem_u32(sVl);
    const uint32_t aBh = smem_u32(sBh), aBl = smem_u32(sBl);
    const uint32_t aFh = smem_u32(sFh), aFl = smem_u32(sFl);

    const int npair = (nh == 0) ? 2 : 1;     // B ldsm pairs owned
    const int pbase = (nh == 0) ? 0 : 2;
    const int nfr = 2 * npair;               // acc frags used

    // ---- one-time init: S, z, sV ones/zero rows, sB zero rows+pad cols ----
    for (int idx = tid; idx < 9216; idx += 512) sSf[idx] = 0.f;
    for (int idx = tid; idx < 288; idx += 512) sZf[idx] = 0.f;
    for (int idx = tid; idx < 8 * 128; idx += 512) {
        int e = 32 + (idx >> 7), j = idx & 127;
        sVh[e * LDV + j] = __float2bfloat16(e == 32 ? 1.f : 0.f);
        sVl[e * LDV + j] = __float2bfloat16(0.f);
    }
    for (int idx = tid; idx < 7 * LDB; idx += 512) {
        int e = 33 + idx / LDB, d = idx % LDB;
        sBh[e * LDB + d] = __float2bfloat16(0.f);
        sBl[e * LDB + d] = __float2bfloat16(0.f);
    }
    for (int idx = tid; idx < 33 * 8; idx += 512) {   // pad cols 144..151 rows 0..32
        int e = idx >> 3, d = 144 + (idx & 7);
        sBh[e * LDB + d] = __float2bfloat16(0.f);
        sBl[e * LDB + d] = __float2bfloat16(0.f);
    }
    __syncthreads();

    for (int c = 0; c < 16; ++c) {
        const int m0 = b * 2048 + c * 128;

        // ---- load q,k (fp32 + hi/lo) and V^T half ----
        for (int idx = tid; idx < 2048; idx += 512) {
            int i = idx >> 4, f = idx & 15;
            float qv = gQKV[(size_t)(m0 + i) * 1536 + h * 16 + f];
            float kv = gQKV[(size_t)(m0 + i) * 1536 + 256 + h * 16 + f];
            sQ[i * 17 + f] = qv;
            sK[i * 17 + f] = kv;
            __nv_bfloat16 qh = __float2bfloat16(qv);
            sQh[i * LDQK + f] = qh;
            sQl[i * LDQK + f] = __float2bfloat16(qv - __bfloat162float(qh));
            __nv_bfloat16 kh = __float2bfloat16(kv);
            sKh[i * LDQK + f] = kh;
            sKl[i * LDQK + f] = __float2bfloat16(kv - __bfloat162float(kh));
        }
        for (int idx = tid; idx < 4096; idx += 512) {
            int j = idx >> 5, e = idx & 31;
            float v = gQKV[(size_t)(m0 + j) * 1536 + 512 + h * 64 + e0 + e];
            __nv_bfloat16 hv = __float2bfloat16(v);
            sVh[e * LDV + j] = hv;
            sVl[e * LDV + j] = __float2bfloat16(v - __bfloat162float(hv));
        }
        __syncthreads();

        // ---- step1: dot MMA + poly/mask + in-register repack ----
        uint32_t ah2[8][4], al2[8][4];
        {
            uint32_t qh4[4], ql4[4];
            uint32_t bo = (uint32_t)(wgrp * 16 + (l & 15)) * (LDQK * 2) + ((l >> 4) << 4);
            ldsm4(qh4, aQh + bo);
            ldsm4(ql4, aQl + bo);
            const int r_lo = wgrp * 16 + (l >> 2);
#pragma unroll
            for (int h2 = 0; h2 < 2; ++h2) {
                float dacc[8][4];
#pragma unroll
                for (int nf = 0; nf < 8; ++nf)
#pragma unroll
                    for (int cc = 0; cc < 4; ++cc) dacc[nf][cc] = 0.f;
#pragma unroll
                for (int pp = 0; pp < 4; ++pp) {
                    int p = h2 * 4 + pp;
                    uint32_t n = (uint32_t)(p * 16 + (l & 7) + ((l >> 4) << 3));
                    uint32_t kb = n * (LDQK * 2) + (((l >> 3) & 1) << 4);
                    uint32_t rk[4], rkl[4];
                    ldsm4(rk, aKh + kb);
                    ldsm4(rkl, aKl + kb);
                    uint32_t b0[2] = {rk[0], rk[1]}, b1[2] = {rk[2], rk[3]};
                    uint32_t c0[2] = {rkl[0], rkl[1]}, c1[2] = {rkl[2], rkl[3]};
                    mma_bf16(dacc[2 * pp], qh4, b0);
                    mma_bf16(dacc[2 * pp], qh4, c0);
                    mma_bf16(dacc[2 * pp], ql4, b0);
                    mma_bf16(dacc[2 * pp + 1], qh4, b1);
                    mma_bf16(dacc[2 * pp + 1], qh4, c1);
                    mma_bf16(dacc[2 * pp + 1], ql4, b1);
                }
#pragma unroll
                for (int nf = 0; nf < 8; ++nf) {
                    int colb = (h2 * 8 + nf) * 8 + 2 * (l & 3);
#pragma unroll
                    for (int cc = 0; cc < 4; ++cc) {
                        int col = colb + (cc & 1);
                        int row = r_lo + ((cc >> 1) << 3);
                        float dot = dacc[nf][cc];
                        float a = 1.f + dot * 0.25f + dot * dot * 0.03125f;
                        dacc[nf][cc] = (col <= row) ? a : 0.f;
                    }
                }
#pragma unroll
                for (int t = 0; t < 4; ++t) {
                    int ksg = h2 * 4 + t;
                    ah2[ksg][0] = hipack(dacc[2 * t][0], dacc[2 * t][1]);
                    ah2[ksg][1] = hipack(dacc[2 * t][2], dacc[2 * t][3]);
                    ah2[ksg][2] = hipack(dacc[2 * t + 1][0], dacc[2 * t + 1][1]);
                    ah2[ksg][3] = hipack(dacc[2 * t + 1][2], dacc[2 * t + 1][3]);
                    al2[ksg][0] = lopack(dacc[2 * t][0], dacc[2 * t][1]);
                    al2[ksg][1] = lopack(dacc[2 * t][2], dacc[2 * t][3]);
                    al2[ksg][2] = lopack(dacc[2 * t + 1][0], dacc[2 * t + 1][1]);
                    al2[ksg][3] = lopack(dacc[2 * t + 1][2], dacc[2 * t + 1][3]);
                }
            }
        }

        float acc[4][4];
#pragma unroll
        for (int nf = 0; nf < 4; ++nf)
#pragma unroll
            for (int cc = 0; cc < 4; ++cc) acc[nf][cc] = 0.f;

        // ---- step2: intra-chunk attn @ [V^T|1] ----
#pragma unroll
        for (int ks = 0; ks < 8; ++ks) {
            uint32_t bhf[4][2], blf[4][2];
#pragma unroll
            for (int pp = 0; pp < 2; ++pp) if (pp < npair) {
                int p = pbase + pp;
                uint32_t n = (uint32_t)(p * 16 + (l & 7) + ((l >> 4) << 3));
                uint32_t bo = n * (LDV * 2) + ks * 32 + (((l >> 3) & 1) << 4);
                uint32_t r4[4];
                ldsm4(r4, aVh + bo);
                bhf[2 * pp][0] = r4[0]; bhf[2 * pp][1] = r4[1];
                bhf[2 * pp + 1][0] = r4[2]; bhf[2 * pp + 1][1] = r4[3];
                ldsm4(r4, aVl + bo);
                blf[2 * pp][0] = r4[0]; blf[2 * pp][1] = r4[1];
                blf[2 * pp + 1][0] = r4[2]; blf[2 * pp + 1][1] = r4[3];
            }
#pragma unroll
            for (int nf = 0; nf < 4; ++nf) if (nf < nfr) {
                mma_bf16(acc[nf], ah2[ks], bhf[nf]);
                mma_bf16(acc[nf], ah2[ks], blf[nf]);
                mma_bf16(acc[nf], al2[ks], bhf[nf]);
            }
        }
        __syncthreads();

        // ---- step3: inter-chunk qf @ [S^T|z], 2 d-slices ----
        for (int sl = 0; sl < 2; ++sl) {
            const int d0 = sl * DSL;
            // qf slice [i][dloc]
            {
                const int i = tid >> 2, qtr = tid & 3;
                const float* qp = sQ + i * 17;
#pragma unroll
                for (int dd = 0; dd < 36; ++dd) {
                    int dloc = qtr * 36 + dd;
                    int d = d0 + dloc;
                    float val;
                    if (d == 0) val = 1.f;
                    else if (d < 17) val = qp[d - 1] * 0.5f;
                    else if (d < DE) { int t = d - 17; val = qp[t >> 4] * qp[t & 15] * C2F; }
                    else val = 0.f;
                    __nv_bfloat16 hv = __float2bfloat16(val);
                    sFh[i * LDFQ + dloc] = hv;
                    sFl[i * LDFQ + dloc] = __float2bfloat16(val - __bfloat162float(hv));
                }
            }
            // B slice: rows 0..31 from S, row 32 = z
            for (int idx = tid; idx < 33 * DSL; idx += 512) {
                int e = idx / DSL, dl = idx % DSL;
                int d = d0 + dl;
                float v = (e < 32) ? sSf[d * 32 + e] : sZf[d];
                __nv_bfloat16 hv = __float2bfloat16(v);
                sBh[e * LDB + dl] = hv;
                sBl[e * LDB + dl] = __float2bfloat16(v - __bfloat162float(hv));
            }
            __syncthreads();

            for (int ks = 0; ks < 9; ++ks) {
                uint32_t ah[4], al[4];
                {
                    uint32_t bo = (uint32_t)(wgrp * 16 + (l & 15)) * (LDFQ * 2)
                                + ks * 32 + ((l >> 4) << 4);
                    ldsm4(ah, aFh + bo);
                    ldsm4(al, aFl + bo);
                }
                uint32_t bhf[4][2], blf[4][2];
#pragma unroll
                for (int pp = 0; pp < 2; ++pp) if (pp < npair) {
                    int p = pbase + pp;
                    uint32_t n = (uint32_t)(p * 16 + (l & 7) + ((l >> 4) << 3));
                    uint32_t bo = n * (LDB * 2) + ks * 32 + (((l >> 3) & 1) << 4);
                    uint32_t r4[4];
                    ldsm4(r4, aBh + bo);
                    bhf[2 * pp][0] = r4[0]; bhf[2 * pp][1] = r4[1];
                    bhf[2 * pp + 1][0] = r4[2]; bhf[2 * pp + 1][1] = r4[3];
                    ldsm4(r4, aBl + bo);
                    blf[2 * pp][0] = r4[0]; blf[2 * pp][1] = r4[1];
                    blf[2 * pp + 1][0] = r4[2]; blf[2 * pp + 1][1] = r4[3];
                }
#pragma unroll
                for (int nf = 0; nf < 4; ++nf) if (nf < nfr) {
                    mma_bf16(acc[nf], ah, bhf[nf]);
                    mma_bf16(acc[nf], ah, blf[nf]);
                    mma_bf16(acc[nf], al, bhf[nf]);
                }
            }
            __syncthreads();
        }

        // ---- denominator exchange + y writeback ----
        if (nh == 1) {   // acc[0] = cols 32.. (col 32 = den)
            float den0 = __shfl_sync(0xffffffffu, acc[0][0], l & 28);
            float den1 = __shfl_sync(0xffffffffu, acc[0][2], l & 28);
            if ((l & 3) == 0) {
                sDen[wgrp * 16 + (l >> 2)] = 1.f / (den0 + EPSV);
                sDen[wgrp * 16 + (l >> 2) + 8] = 1.f / (den1 + EPSV);
            }
        }
        __syncthreads();
        if (nh == 0) {
            float inv0 = sDen[wgrp * 16 + (l >> 2)];
            float inv1 = sDen[wgrp * 16 + (l >> 2) + 8];
#pragma unroll
            for (int nf = 0; nf < 4; ++nf) {
                int ecol = nf * 8 + 2 * (l & 3);
#pragma unroll
                for (int hh = 0; hh < 2; ++hh) {
                    int row = wgrp * 16 + (l >> 2) + hh * 8;
                    float inv = hh ? inv1 : inv0;
                    size_t base = (size_t)(m0 + row) * 1024 + h * 64 + e0 + ecol;
#pragma unroll
                    for (int cc = 0; cc < 2; ++cc) {
                        float yv = acc[nf][hh * 2 + cc] * inv;
                        __nv_bfloat16 hv = __float2bfloat16(yv);
                        gYh[base + cc] = hv;
                        gYl[base + cc] = __float2bfloat16(yv - __bfloat162float(hv));
                    }
                }
            }
        }

        // ---- update: S += kf^T @ [V^T|1], 2 d-slices of 144 ----
        const int nmf = (wgrp == 0) ? 2 : 1;
        for (int sl = 0; sl < 2; ++sl) {
            const int d0 = sl * DSL;
            // kf slice [dloc][j]
            for (int idx = tid; idx < DSL * 128; idx += 512) {
                int dl = idx >> 7, j = idx & 127;
                int d = d0 + dl;
                float val;
                if (d == 0) val = 1.f;
                else if (d < 17) val = sK[j * 17 + d - 1] * 0.5f;
                else if (d < DE) { int t = d - 17; val = sK[j * 17 + (t >> 4)] * sK[j * 17 + (t & 15)] * C2F; }
                else val = 0.f;
                __nv_bfloat16 hv = __float2bfloat16(val);
                sFh[dl * LDFK + j] = hv;
                sFl[dl * LDFK + j] = __float2bfloat16(val - __bfloat162float(hv));
            }
            __syncthreads();

            float uacc[2][4][4];
#pragma unroll
            for (int r = 0; r < 2; ++r)
#pragma unroll
                for (int nf = 0; nf < 4; ++nf)
#pragma unroll
                    for (int cc = 0; cc < 4; ++cc) uacc[r][nf][cc] = 0.f;

#pragma unroll
            for (int ks = 0; ks < 8; ++ks) {
                uint32_t ah[2][4], al[2][4];
#pragma unroll
                for (int r = 0; r < 2; ++r) if (r < nmf) {
                    int mf = wgrp + 8 * r;
                    uint32_t bo = (uint32_t)(mf * 16 + (l & 15)) * (LDFK * 2)
                                + ks * 32 + ((l >> 4) << 4);
                    ldsm4(ah[r], aFh + bo);
                    ldsm4(al[r], aFl + bo);
                }
                uint32_t bhf[4][2], blf[4][2];
#pragma unroll
                for (int pp = 0; pp < 2; ++pp) if (pp < npair) {
                    int p = pbase + pp;
                    uint32_t n = (uint32_t)(p * 16 + (l & 7) + ((l >> 4) << 3));
                    uint32_t bo = n * (LDV * 2) + ks * 32 + (((l >> 3) & 1) << 4);
                    uint32_t r4[4];
                    ldsm4(r4, aVh + bo);
                    bhf[2 * pp][0] = r4[0]; bhf[2 * pp][1] = r4[1];
                    bhf[2 * pp + 1][0] = r4[2]; bhf[2 * pp + 1][1] = r4[3];
                    ldsm4(r4, aVl + bo);
                    blf[2 * pp][0] = r4[0]; blf[2 * pp][1] = r4[1];
                    blf[2 * pp + 1][0] = r4[2]; blf[2 * pp + 1][1] = r4[3];
                }
#pragma unroll
                for (int r = 0; r < 2; ++r) if (r < nmf)
#pragma unroll
                    for (int nf = 0; nf < 4; ++nf) if (nf < nfr) {
                        mma_bf16(uacc[r][nf], ah[r], bhf[nf]);
                        mma_bf16(uacc[r][nf], ah[r], blf[nf]);
                        mma_bf16(uacc[r][nf], al[r], bhf[nf]);
                    }
            }

            // accumulate into S / z (disjoint (d,e) per warp)
#pragma unroll
            for (int r = 0; r < 2; ++r) if (r < nmf) {
                int mf = wgrp + 8 * r;
                int dl0 = mf * 16 + (l >> 2);
#pragma unroll
                for (int hh = 0; hh < 2; ++hh) {
                    int d = d0 + dl0 + hh * 8;
                    if (nh == 0) {
#pragma unroll
                        for (int nf = 0; nf < 4; ++nf) {
                            int e = nf * 8 + 2 * (l & 3);
                            sSf[d * 32 + e]     += uacc[r][nf][hh * 2];
                            sSf[d * 32 + e + 1] += uacc[r][nf][hh * 2 + 1];
                        }
                    } else if ((l & 3) == 0) {
                        sZf[d] += uacc[r][0][hh * 2];
                    }
                }
            }
            __syncthreads();
        }
    }
}

// ============================================================================
// host launch
// ============================================================================
extern "C" void kernel_launch(void* const* d_in, const int* in_sizes, int n_in,
                              void* d_out, int out_size)
{
    const float* hs = (const float*)d_in[0];
    const float* Wq = (const float*)d_in[1];
    const float* Wk = (const float*)d_in[2];
    const float* Wv = (const float*)d_in[3];
    const float* Wo = (const float*)d_in[4];
    float* out = (float*)d_out;

    float* pQKV;
    __nv_bfloat16 *pHh, *pHl, *pWh, *pWl, *pWoh, *pWol, *pYh, *pYl;
    cudaGetSymbolAddress((void**)&pQKV, gQKV);
    cudaGetSymbolAddress((void**)&pHh, gHh);
    cudaGetSymbolAddress((void**)&pHl, gHl);
    cudaGetSymbolAddress((void**)&pWh, gWh);
    cudaGetSymbolAddress((void**)&pWl, gWl);
    cudaGetSymbolAddress((void**)&pWoh, gWoh);
    cudaGetSymbolAddress((void**)&pWol, gWol);
    cudaGetSymbolAddress((void**)&pYh, gYh);
    cudaGetSymbolAddress((void**)&pYl, gYl);

    const int SMEM_G = 131072;     // 2 x 64KB
    const int SMEM_A = 204928;     // attn_persist carve (see layout)
    cudaFuncSetAttribute(gemm_mma,
                         cudaFuncAttributeMaxDynamicSharedMemorySize, SMEM_G);
    cudaFuncSetAttribute(attn_persist,
                         cudaFuncAttributeMaxDynamicSharedMemorySize, SMEM_A);

    // (launch order keeps attn_persist in the profiled slot)
    cvt_hilo<<<8192, 256>>>(hs, pHh, pHl);
    cvt3_w<<<1536, 256>>>(Wq, Wk, Wv, pWh, pWl);

    // fused Q|K|V projection (N = 1536)
    gemm_mma<<<dim3(12, 64), 512, SMEM_G>>>(pHh, pHl, pWh, pWl, pQKV, 1536, 1024);

    // chunked linear attention, state resident in SMEM
    attn_persist<<<128, 512, SMEM_A>>>();

    // output projection
    cvt_hilo<<<1024, 256>>>(Wo, pWoh, pWol);
    gemm_mma<<<dim3(8, 64), 512, SMEM_G>>>(pYh, pYl, pWoh, pWol, out, 1024, 1024);
}

// round 14
// speedup vs baseline: 1.1688x; 1.1688x over previous
#include <cuda_runtime.h>
#include <cuda_bf16.h>
#include <cstdint>

#define DE 273
#define EPSV 1e-12f
#define C2F 0.17677669529663688f  // 1/(4*sqrt(2))

// ----- scratch (static device allocations; no cudaMalloc allowed) -----
__device__ float gQKV[8192 * 1536];        // [m][0:256 Q | 256:512 K | 512:1536 V]
__device__ float gS[1024 * 65 * 288];      // per-chunk S^T|z fp32: [bid][e 0..64][d 0..287]
__device__ __nv_bfloat16 gSh[1024 * 65 * 288];  // exclusive-prefixed, bf16 hi
__device__ __nv_bfloat16 gSl[1024 * 65 * 288];  // exclusive-prefixed, bf16 lo
__device__ __nv_bfloat16 gHh[8192 * 1024];
__device__ __nv_bfloat16 gHl[8192 * 1024];
__device__ __nv_bfloat16 gWh[1536 * 1024];
__device__ __nv_bfloat16 gWl[1536 * 1024];
__device__ __nv_bfloat16 gWoh[1024 * 1024];
__device__ __nv_bfloat16 gWol[1024 * 1024];
__device__ __nv_bfloat16 gYh[8192 * 1024];
__device__ __nv_bfloat16 gYl[8192 * 1024];

// ============================================================================
// helpers (portable PTX only: cp.async / ldmatrix / mma.sync)
// ============================================================================
__device__ __forceinline__ uint32_t smem_u32(const void* p) {
    uint32_t a;
    asm("{ .reg .u64 t; cvta.to.shared.u64 t, %1; cvt.u32.u64 %0, t; }" : "=r"(a) : "l"(p));
    return a;
}
__device__ __forceinline__ void cpasync16(uint32_t dst, const void* src) {
    asm volatile("cp.async.cg.shared.global [%0], [%1], 16;" :: "r"(dst), "l"(src));
}
__device__ __forceinline__ void cpasync_commit() {
    asm volatile("cp.async.commit_group;" ::: "memory");
}
__device__ __forceinline__ void cpasync_wait_all() {
    asm volatile("cp.async.wait_group 0;" ::: "memory");
}
__device__ __forceinline__ void ldsm4(uint32_t* r, uint32_t addr) {
    asm volatile("ldmatrix.sync.aligned.m8n8.x4.shared.b16 {%0,%1,%2,%3}, [%4];"
        : "=r"(r[0]), "=r"(r[1]), "=r"(r[2]), "=r"(r[3]) : "r"(addr));
}
__device__ __forceinline__ void mma_bf16(float* d, const uint32_t* a, const uint32_t* b) {
    asm volatile(
        "mma.sync.aligned.m16n8k16.row.col.f32.bf16.bf16.f32 "
        "{%0,%1,%2,%3}, {%4,%5,%6,%7}, {%8,%9}, {%0,%1,%2,%3};"
        : "+f"(d[0]), "+f"(d[1]), "+f"(d[2]), "+f"(d[3])
        : "r"(a[0]), "r"(a[1]), "r"(a[2]), "r"(a[3]), "r"(b[0]), "r"(b[1]));
}
__device__ __forceinline__ uint32_t sw128(uint32_t bo) { return bo ^ ((bo >> 3) & 0x70); }
__device__ __forceinline__ uint32_t hipack(float x, float y) {
    __nv_bfloat162 h(__float2bfloat16(x), __float2bfloat16(y));
    return *(uint32_t*)&h;
}
__device__ __forceinline__ uint32_t lopack(float x, float y) {
    float xr = x - __bfloat162float(__float2bfloat16(x));
    float yr = y - __bfloat162float(__float2bfloat16(y));
    __nv_bfloat162 h(__float2bfloat16(xr), __float2bfloat16(yr));
    return *(uint32_t*)&h;
}

// ============================================================================
// fp32 -> (hi, lo) bf16 split conversions
// ============================================================================
__device__ __forceinline__ void cvt_body(const float* __restrict__ src,
                                         __nv_bfloat16* __restrict__ hi,
                                         __nv_bfloat16* __restrict__ lo, int i)
{
    float4 v = *(const float4*)(src + i);
    __nv_bfloat16 h0 = __float2bfloat16(v.x), h1 = __float2bfloat16(v.y);
    __nv_bfloat16 h2 = __float2bfloat16(v.z), h3 = __float2bfloat16(v.w);
    __nv_bfloat16 l0 = __float2bfloat16(v.x - __bfloat162float(h0));
    __nv_bfloat16 l1 = __float2bfloat16(v.y - __bfloat162float(h1));
    __nv_bfloat16 l2 = __float2bfloat16(v.z - __bfloat162float(h2));
    __nv_bfloat16 l3 = __float2bfloat16(v.w - __bfloat162float(h3));
    __nv_bfloat162* ph = (__nv_bfloat162*)(hi + i);
    __nv_bfloat162* pl = (__nv_bfloat162*)(lo + i);
    ph[0] = __nv_bfloat162(h0, h1); ph[1] = __nv_bfloat162(h2, h3);
    pl[0] = __nv_bfloat162(l0, l1); pl[1] = __nv_bfloat162(l2, l3);
}

__global__ void __launch_bounds__(256) cvt_hilo(
    const float* __restrict__ src, __nv_bfloat16* __restrict__ hi,
    __nv_bfloat16* __restrict__ lo)
{
    int i = (blockIdx.x * 256 + threadIdx.x) * 4;
    cvt_body(src, hi, lo, i);
}

// Wq (blocks 0..255) | Wk (256..511) | Wv (512..1535) -> contiguous hi/lo
__global__ void __launch_bounds__(256) cvt3_w(
    const float* __restrict__ Wq, const float* __restrict__ Wk,
    const float* __restrict__ Wv, __nv_bfloat16* __restrict__ hi,
    __nv_bfloat16* __restrict__ lo)
{
    int blk = blockIdx.x;
    int i = (blk * 256 + threadIdx.x) * 4;
    const float* src;
    if (blk < 256) src = Wq;
    else if (blk < 512) src = Wk - 256 * 1024;
    else src = Wv - 512 * 1024;
    cvt_body(src, hi, lo, i);
}

// ============================================================================
// split-bf16 HMMA GEMM (NT): C = Ah*Bh + Ah*Bl + Al*Bh, fp32-quality.
// CTA tile 128x128, K stages of 64, 2-stage cp.async, SW128.  512 thr.
// ============================================================================
__global__ void __launch_bounds__(512, 1) gemm_mma(
    const __nv_bfloat16* __restrict__ Ah, const __nv_bfloat16* __restrict__ Al,
    const __nv_bfloat16* __restrict__ Bh, const __nv_bfloat16* __restrict__ Bl,
    float* __restrict__ C, int N, int K)
{
    extern __shared__ char smem[];
    const uint32_t sb = smem_u32(smem);
    const int tid = threadIdx.x, wid = tid >> 5, l = tid & 31;
    const int wm = wid & 3, wn = wid >> 2;
    const int bm = blockIdx.y * 128, bn = blockIdx.x * 128;

    const __nv_bfloat16* gp0[4] = {
        Ah + (size_t)bm * K, Al + (size_t)bm * K,
        Bh + (size_t)bn * K, Bl + (size_t)bn * K };

    const int NST = K >> 6;

    float acc[2][4][4];
#pragma unroll
    for (int mt = 0; mt < 2; ++mt)
#pragma unroll
        for (int nt = 0; nt < 4; ++nt)
#pragma unroll
            for (int c = 0; c < 4; ++c) acc[mt][nt][c] = 0.f;

    {
        const uint32_t sdst = sb;
#pragma unroll
        for (int t = 0; t < 4; ++t)
#pragma unroll
            for (int it = 0; it < 2; ++it) {
                int ch = tid + it * 512;
                int row = ch >> 3, cb = ch & 7;
                cpasync16(sdst + t * 16384 + sw128(row * 128 + cb * 16),
                          gp0[t] + (size_t)row * K + cb * 8);
            }
        cpasync_commit();
    }

    for (int s = 0; s < NST; ++s) {
        cpasync_wait_all();
        __syncthreads();
        if (s + 1 < NST) {
            const uint32_t sdst = sb + (uint32_t)((s + 1) & 1) * 65536u;
            const int k0 = (s + 1) * 64;
#pragma unroll
            for (int t = 0; t < 4; ++t)
#pragma unroll
                for (int it = 0; it < 2; ++it) {
                    int ch = tid + it * 512;
                    int row = ch >> 3, cb = ch & 7;
                    cpasync16(sdst + t * 16384 + sw128(row * 128 + cb * 16),
                              gp0[t] + (size_t)row * K + k0 + cb * 8);
                }
            cpasync_commit();
        }
        const uint32_t sc = sb + (uint32_t)(s & 1) * 65536u;
#pragma unroll
        for (int ks = 0; ks < 4; ++ks) {
            uint32_t ah[2][4], al[2][4];
#pragma unroll
            for (int mt = 0; mt < 2; ++mt) {
                uint32_t bo = (uint32_t)(wm * 32 + mt * 16 + (l & 15)) * 128
                            + ks * 32 + ((l >> 4) << 4);
                bo = sw128(bo);
                ldsm4(ah[mt], sc + bo);
                ldsm4(al[mt], sc + 16384 + bo);
            }
#pragma unroll
            for (int p = 0; p < 2; ++p) {
                uint32_t n = (uint32_t)(wn * 32 + p * 16 + (l & 7) + ((l >> 4) << 3));
                uint32_t bo = n * 128 + ks * 32 + (((l >> 3) & 1) << 4);
                bo = sw128(bo);
                uint32_t rb[4], rl[4];
                ldsm4(rb, sc + 32768 + bo);
                ldsm4(rl, sc + 49152 + bo);
                uint32_t b0[2] = {rb[0], rb[1]}, b1[2] = {rb[2], rb[3]};
                uint32_t c0[2] = {rl[0], rl[1]}, c1[2] = {rl[2], rl[3]};
#pragma unroll
                for (int mt = 0; mt < 2; ++mt) {
                    mma_bf16(acc[mt][2 * p],     ah[mt], b0);
                    mma_bf16(acc[mt][2 * p + 1], ah[mt], b1);
                    mma_bf16(acc[mt][2 * p],     ah[mt], c0);
                    mma_bf16(acc[mt][2 * p + 1], ah[mt], c1);
                    mma_bf16(acc[mt][2 * p],     al[mt], b0);
                    mma_bf16(acc[mt][2 * p + 1], al[mt], b1);
                }
            }
        }
        __syncthreads();
    }

    const int r0 = bm + wm * 32 + (l >> 2);
    const int c0 = bn + wn * 32 + 2 * (l & 3);
#pragma unroll
    for (int mt = 0; mt < 2; ++mt)
#pragma unroll
        for (int nt = 0; nt < 4; ++nt) {
            float* p0 = C + (size_t)(r0 + mt * 16) * N + c0 + nt * 8;
            float* p1 = C + (size_t)(r0 + mt * 16 + 8) * N + c0 + nt * 8;
            *(float2*)p0 = make_float2(acc[mt][nt][0], acc[mt][nt][1]);
            *(float2*)p1 = make_float2(acc[mt][nt][2], acc[mt][nt][3]);
        }
}

// ============================================================================
// Phase A (MMA, 3-pass): per-(bh,c) S_c = kf^T @ v, z via ones-column.
// Writes S^T|z fp32 in [e 0..64][d 0..287] layout (z = row 64).
// 512 threads, 16 warps = 8 m-slots x 2 n-halves.
// ============================================================================
#define LDA_A 136
__global__ void __launch_bounds__(512, 1) chunk_state_mma()
{
    extern __shared__ char smraw[];
    __nv_bfloat16* sKh = (__nv_bfloat16*)smraw;       // 288*136
    __nv_bfloat16* sKl = sKh + 288 * LDA_A;
    __nv_bfloat16* sVh = sKl + 288 * LDA_A;           // 80*136
    __nv_bfloat16* sVl = sVh + 80 * LDA_A;

    const int bid = blockIdx.x;
    const int bh = bid >> 4, c = bid & 15;
    const int b = bh >> 4, h = bh & 15;
    const int tid = threadIdx.x, wid = tid >> 5, l = tid & 31;
    const int wgrp = wid & 7, nh = wid >> 3;
    const int m0 = b * 2048 + c * 128;

    // ---- build kf^T hi/lo ----
    {
        const int j = tid >> 2, qtr = tid & 3;
        const float* kp = gQKV + (size_t)(m0 + j) * 1536 + 256 + h * 16;
        float kr[16];
#pragma unroll
        for (int f = 0; f < 16; f += 4) {
            float4 v4 = *(const float4*)(kp + f);
            kr[f] = v4.x; kr[f + 1] = v4.y; kr[f + 2] = v4.z; kr[f + 3] = v4.w;
        }
        for (int dd = 0; dd < 72; ++dd) {
            int d = qtr * 72 + dd;
            float val;
            if (d == 0) val = 1.f;
            else if (d < 17) val = kr[d - 1] * 0.5f;
            else if (d < 273) { int t = d - 17; val = kr[t >> 4] * kr[t & 15] * C2F; }
            else val = 0.f;
            __nv_bfloat16 hv = __float2bfloat16(val);
            sKh[d * LDA_A + j] = hv;
            sKl[d * LDA_A + j] = __float2bfloat16(val - __bfloat162float(hv));
        }
    }
    for (int idx = tid; idx < 8192; idx += 512) {
        int j = idx >> 6, e = idx & 63;
        float v = gQKV[(size_t)(m0 + j) * 1536 + 512 + h * 64 + e];
        __nv_bfloat16 hv = __float2bfloat16(v);
        sVh[e * LDA_A + j] = hv;
        sVl[e * LDA_A + j] = __float2bfloat16(v - __bfloat162float(hv));
    }
    for (int idx = tid; idx < 16 * 128; idx += 512) {
        int e = 64 + (idx >> 7), j = idx & 127;
        sVh[e * LDA_A + j] = __float2bfloat16(e == 64 ? 1.f : 0.f);
        sVl[e * LDA_A + j] = __float2bfloat16(0.f);
    }
    __syncthreads();

    const uint32_t aKh = smem_u32(sKh), aKl = smem_u32(sKl);
    const uint32_t aVh = smem_u32(sVh), aVl = smem_u32(sVl);
    const int nmf = (wgrp < 2) ? 3 : 2;
    const int pstart = nh * 2;

    float acc[3][6][4];
#pragma unroll
    for (int r = 0; r < 3; ++r)
#pragma unroll
        for (int nf = 0; nf < 6; ++nf)
#pragma unroll
            for (int cc = 0; cc < 4; ++cc) acc[r][nf][cc] = 0.f;

    for (int ks = 0; ks < 8; ++ks) {
        uint32_t ah[3][4], al[3][4];
#pragma unroll
        for (int r = 0; r < 3; ++r) if (r < nmf) {
            int mf = wgrp + 8 * r;
            uint32_t bo = (uint32_t)(mf * 16 + (l & 15)) * (LDA_A * 2)
                        + ks * 32 + ((l >> 4) << 4);
            ldsm4(ah[r], aKh + bo);
            ldsm4(al[r], aKl + bo);
        }
        uint32_t bhf[6][2], blf[6][2];
#pragma unroll
        for (int pp = 0; pp < 3; ++pp) {
            int p = pstart + pp;
            uint32_t n = (uint32_t)(p * 16 + (l & 7) + ((l >> 4) << 3));
            uint32_t bo = n * (LDA_A * 2) + ks * 32 + (((l >> 3) & 1) << 4);
            uint32_t r4[4];
            ldsm4(r4, aVh + bo);
            bhf[2 * pp][0] = r4[0]; bhf[2 * pp][1] = r4[1];
            bhf[2 * pp + 1][0] = r4[2]; bhf[2 * pp + 1][1] = r4[3];
            ldsm4(r4, aVl + bo);
            blf[2 * pp][0] = r4[0]; blf[2 * pp][1] = r4[1];
            blf[2 * pp + 1][0] = r4[2]; blf[2 * pp + 1][1] = r4[3];
        }
#pragma unroll
        for (int r = 0; r < 3; ++r) if (r < nmf)
#pragma unroll
            for (int nf = 0; nf < 6; ++nf) {
                mma_bf16(acc[r][nf], ah[r], bhf[nf]);
                mma_bf16(acc[r][nf], ah[r], blf[nf]);
                mma_bf16(acc[r][nf], al[r], bhf[nf]);
            }
    }

    // ---- writeback S^T|z: outS[e*288 + d] ----
    float* outS = gS + (size_t)bid * (65 * 288);
#pragma unroll
    for (int r = 0; r < 3; ++r) if (r < nmf) {
        int mf = wgrp + 8 * r;
        int d0r = mf * 16 + (l >> 2);
#pragma unroll
        for (int nf = 0; nf < 6; ++nf) {
            int g = 2 * pstart + nf;
            bool own = nh == 0 ? (g <= 4) : (g >= 5 && g <= 8);
            if (!own) continue;
            int c0 = g * 8 + 2 * (l & 3);
#pragma unroll
            for (int hh = 0; hh < 2; ++hh) {
                int d = d0r + hh * 8;
                if (c0 < 64) {
                    outS[(size_t)c0 * 288 + d]       = acc[r][nf][hh * 2];
                    outS[(size_t)(c0 + 1) * 288 + d] = acc[r][nf][hh * 2 + 1];
                } else if (c0 == 64) {
                    outS[(size_t)64 * 288 + d] = acc[r][nf][hh * 2];
                }
            }
        }
    }
}

// ============================================================================
// Phase B: exclusive prefix over 16 chunks per (b,h); emits bf16 hi/lo
// directly in ldsm-ready [e][d] layout.  8 CTAs per bh.
// ============================================================================
__global__ void __launch_bounds__(256) prefix_kernel()
{
    const int bh = blockIdx.x >> 3, part = blockIdx.x & 7;
    const size_t base = (size_t)bh * 16 * (65 * 288);
    const float* Sb = gS + base;
    __nv_bfloat16* Sh = gSh + base;
    __nv_bfloat16* Sl = gSl + base;
    const int i0 = part * 2340, i1 = i0 + 2340;     // 18720/8
    for (int idx = i0 + threadIdx.x; idx < i1; idx += 256) {
        float run = 0.f;
#pragma unroll
        for (int c = 0; c < 16; ++c) {
            size_t off = (size_t)c * (65 * 288) + idx;
            float tmp = Sb[off];
            __nv_bfloat16 hv = __float2bfloat16(run);
            Sh[off] = hv;
            Sl[off] = __float2bfloat16(run - __bfloat162float(hv));
            run += tmp;
        }
    }
}

// ============================================================================
// Phase C (MMA, 3-pass): per-(bh,c) output.  S/z tiles arrive via cp.async
// (pre-converted bf16 hi/lo from prefix_kernel) — no SIMT transpose/convert.
// 512 threads, 16 warps = 8 m-slots x 2 n-halves.
// ============================================================================
#define LDA_C 152
#define LDQK 24
__global__ void __launch_bounds__(512, 1) chunk_out_mma()
{
    extern __shared__ char smraw[];
    __nv_bfloat16* sAh = (__nv_bfloat16*)smraw;        // 128*152
    __nv_bfloat16* sAl = sAh + 128 * LDA_C;
    __nv_bfloat16* sBh = sAl + 128 * LDA_C;            // 80*152
    __nv_bfloat16* sBl = sBh + 80 * LDA_C;
    float* sQ = (float*)(sBl + 80 * LDA_C);            // 128*17 (reused for den)
    __nv_bfloat16* sQh = (__nv_bfloat16*)(sQ + 128 * 17); // 128*24 each
    __nv_bfloat16* sQl = sQh + 128 * LDQK;
    __nv_bfloat16* sKh = sQl + 128 * LDQK;
    __nv_bfloat16* sKl = sKh + 128 * LDQK;

    const int bid = blockIdx.x;
    const int bh = bid >> 4, c = bid & 15;
    const int b = bh >> 4, h = bh & 15;
    const int tid = threadIdx.x, wid = tid >> 5, l = tid & 31;
    const int wgrp = wid & 7, nh = wid >> 3;
    const int m0 = b * 2048 + c * 128;

    // ---- load q,k; build bf16 hi/lo tiles + fp32 q ----
    for (int idx = tid; idx < 2048; idx += 512) {
        int i = idx >> 4, f = idx & 15;
        float qv = gQKV[(size_t)(m0 + i) * 1536 + h * 16 + f];
        float kv = gQKV[(size_t)(m0 + i) * 1536 + 256 + h * 16 + f];
        sQ[i * 17 + f] = qv;
        __nv_bfloat16 qh = __float2bfloat16(qv);
        sQh[i * LDQK + f] = qh;
        sQl[i * LDQK + f] = __float2bfloat16(qv - __bfloat162float(qh));
        __nv_bfloat16 kh = __float2bfloat16(kv);
        sKh[i * LDQK + f] = kh;
        sKl[i * LDQK + f] = __float2bfloat16(kv - __bfloat162float(kh));
    }
    for (int idx = tid; idx < 8192; idx += 512) {
        int j = idx >> 6, e = idx & 63;
        float v = gQKV[(size_t)(m0 + j) * 1536 + 512 + h * 64 + e];
        __nv_bfloat16 hv = __float2bfloat16(v);
        sBh[e * LDA_C + j] = hv;
        sBl[e * LDA_C + j] = __float2bfloat16(v - __bfloat162float(hv));
    }
    for (int idx = tid; idx < 16 * 144; idx += 512) {
        int e = 64 + (idx / 144), j = idx % 144;
        sBh[e * LDA_C + j] = __float2bfloat16(e == 64 ? 1.f : 0.f);
        sBl[e * LDA_C + j] = __float2bfloat16(0.f);
    }
    __syncthreads();

    const uint32_t aQh = smem_u32(sQh), aQl = smem_u32(sQl);
    const uint32_t aKh = smem_u32(sKh), aKl = smem_u32(sKl);
    const uint32_t aAh = smem_u32(sAh), aAl = smem_u32(sAl);
    const uint32_t aBh = smem_u32(sBh), aBl = smem_u32(sBl);
    const int pstart = nh * 2;

    // ---- step1: dot MMA (3-pass) + poly/mask + in-register repack ----
    uint32_t ah2[8][4], al2[8][4];
    {
        uint32_t qh4[4], ql4[4];
        uint32_t bo = (uint32_t)(wgrp * 16 + (l & 15)) * (LDQK * 2) + ((l >> 4) << 4);
        ldsm4(qh4, aQh + bo);
        ldsm4(ql4, aQl + bo);
        const int r_lo = wgrp * 16 + (l >> 2);
#pragma unroll
        for (int h2 = 0; h2 < 2; ++h2) {
            float dacc[8][4];
#pragma unroll
            for (int nf = 0; nf < 8; ++nf)
#pragma unroll
                for (int cc = 0; cc < 4; ++cc) dacc[nf][cc] = 0.f;
#pragma unroll
            for (int pp = 0; pp < 4; ++pp) {
                int p = h2 * 4 + pp;
                uint32_t n = (uint32_t)(p * 16 + (l & 7) + ((l >> 4) << 3));
                uint32_t kb = n * (LDQK * 2) + (((l >> 3) & 1) << 4);
                uint32_t rk[4], rkl[4];
                ldsm4(rk, aKh + kb);
                ldsm4(rkl, aKl + kb);
                uint32_t b0[2] = {rk[0], rk[1]}, b1[2] = {rk[2], rk[3]};
                uint32_t c0[2] = {rkl[0], rkl[1]}, c1[2] = {rkl[2], rkl[3]};
                mma_bf16(dacc[2 * pp], qh4, b0);
                mma_bf16(dacc[2 * pp], qh4, c0);
                mma_bf16(dacc[2 * pp], ql4, b0);
                mma_bf16(dacc[2 * pp + 1], qh4, b1);
                mma_bf16(dacc[2 * pp + 1], qh4, c1);
                mma_bf16(dacc[2 * pp + 1], ql4, b1);
            }
#pragma unroll
            for (int nf = 0; nf < 8; ++nf) {
                int colb = (h2 * 8 + nf) * 8 + 2 * (l & 3);
#pragma unroll
                for (int cc = 0; cc < 4; ++cc) {
                    int col = colb + (cc & 1);
                    int row = r_lo + ((cc >> 1) << 3);
                    float dot = dacc[nf][cc];
                    float a = 1.f + dot * 0.25f + dot * dot * 0.03125f;
                    dacc[nf][cc] = (col <= row) ? a : 0.f;
                }
            }
#pragma unroll
            for (int t = 0; t < 4; ++t) {
                int ksg = h2 * 4 + t;
                ah2[ksg][0] = hipack(dacc[2 * t][0], dacc[2 * t][1]);
                ah2[ksg][1] = hipack(dacc[2 * t][2], dacc[2 * t][3]);
                ah2[ksg][2] = hipack(dacc[2 * t + 1][0], dacc[2 * t + 1][1]);
                ah2[ksg][3] = hipack(dacc[2 * t + 1][2], dacc[2 * t + 1][3]);
                al2[ksg][0] = lopack(dacc[2 * t][0], dacc[2 * t][1]);
                al2[ksg][1] = lopack(dacc[2 * t][2], dacc[2 * t][3]);
                al2[ksg][2] = lopack(dacc[2 * t + 1][0], dacc[2 * t + 1][1]);
                al2[ksg][3] = lopack(dacc[2 * t + 1][2], dacc[2 * t + 1][3]);
            }
        }
    }

    float acc[6][4];
#pragma unroll
    for (int nf = 0; nf < 6; ++nf)
#pragma unroll
        for (int cc = 0; cc < 4; ++cc) acc[nf][cc] = 0.f;

    // ---- step2: intra-chunk MMA (attn hi/lo in registers) ----
#pragma unroll
    for (int ks = 0; ks < 8; ++ks) {
        uint32_t bhf[6][2], blf[6][2];
#pragma unroll
        for (int pp = 0; pp < 3; ++pp) {
            int p = pstart + pp;
            uint32_t n = (uint32_t)(p * 16 + (l & 7) + ((l >> 4) << 3));
            uint32_t bo = n * (LDA_C * 2) + ks * 32 + (((l >> 3) & 1) << 4);
            uint32_t r4[4];
            ldsm4(r4, aBh + bo);
            bhf[2 * pp][0] = r4[0]; bhf[2 * pp][1] = r4[1];
            bhf[2 * pp + 1][0] = r4[2]; bhf[2 * pp + 1][1] = r4[3];
            ldsm4(r4, aBl + bo);
            blf[2 * pp][0] = r4[0]; blf[2 * pp][1] = r4[1];
            blf[2 * pp + 1][0] = r4[2]; blf[2 * pp + 1][1] = r4[3];
        }
#pragma unroll
        for (int nf = 0; nf < 6; ++nf) {
            mma_bf16(acc[nf], ah2[ks], bhf[nf]);
            mma_bf16(acc[nf], ah2[ks], blf[nf]);
            mma_bf16(acc[nf], al2[ks], bhf[nf]);
        }
    }
    __syncthreads();

    // ---- step3: inter-chunk, 2 d-tiles of 144; S/z via cp.async ----
    const __nv_bfloat16* Sph = gSh + (size_t)bid * (65 * 288);
    const __nv_bfloat16* Spl = gSl + (size_t)bid * (65 * 288);
    for (int dt = 0; dt < 2; ++dt) {
        const int d0 = dt * 144;
        // issue async S/z tile copies (65 rows x 18 chunks of 16B, hi+lo)
        for (int idx = tid; idx < 65 * 18; idx += 512) {
            int e = idx / 18, ch = idx % 18;
            uint32_t so = (uint32_t)(e * LDA_C * 2 + ch * 16);
            const size_t go = (size_t)e * 288 + d0 + ch * 8;
            cpasync16(aBh + so, Sph + go);
            cpasync16(aBl + so, Spl + go);
        }
        cpasync_commit();
        // qf tile (SIMT, overlapped with the copies)
        {
            const int i = tid >> 2, qtr = tid & 3;
            const float* qp = sQ + i * 17;
            for (int dd = 0; dd < 36; ++dd) {
                int dloc = qtr * 36 + dd;
                int d = d0 + dloc;
                float val;
                if (d == 0) val = 1.f;
                else if (d < 17) val = qp[d - 1] * 0.5f;
                else if (d < 273) { int t = d - 17; val = qp[t >> 4] * qp[t & 15] * C2F; }
                else val = 0.f;
                __nv_bfloat16 hv = __float2bfloat16(val);
                sAh[i * LDA_C + dloc] = hv;
                sAl[i * LDA_C + dloc] = __float2bfloat16(val - __bfloat162float(hv));
            }
        }
        cpasync_wait_all();
        __syncthreads();

        for (int ks = 0; ks < 9; ++ks) {
            uint32_t ah[4], al[4];
            {
                uint32_t bo = (uint32_t)(wgrp * 16 + (l & 15)) * (LDA_C * 2)
                            + ks * 32 + ((l >> 4) << 4);
                ldsm4(ah, aAh + bo);
                ldsm4(al, aAl + bo);
            }
            uint32_t bhf[6][2], blf[6][2];
#pragma unroll
            for (int pp = 0; pp < 3; ++pp) {
                int p = pstart + pp;
                uint32_t n = (uint32_t)(p * 16 + (l & 7) + ((l >> 4) << 3));
                uint32_t bo = n * (LDA_C * 2) + ks * 32 + (((l >> 3) & 1) << 4);
                uint32_t r4[4];
                ldsm4(r4, aBh + bo);
                bhf[2 * pp][0] = r4[0]; bhf[2 * pp][1] = r4[1];
                bhf[2 * pp + 1][0] = r4[2]; bhf[2 * pp + 1][1] = r4[3];
                ldsm4(r4, aBl + bo);
                blf[2 * pp][0] = r4[0]; blf[2 * pp][1] = r4[1];
                blf[2 * pp + 1][0] = r4[2]; blf[2 * pp + 1][1] = r4[3];
            }
#pragma unroll
            for (int nf = 0; nf < 6; ++nf) {
                mma_bf16(acc[nf], ah, bhf[nf]);
                mma_bf16(acc[nf], ah, blf[nf]);
                mma_bf16(acc[nf], al, bhf[nf]);
            }
        }
        __syncthreads();
    }

    // ---- denominator exchange (nh1 owns g=8) then divide + store ----
    const int rowbase = wgrp * 16;
    if (nh == 1) {
        float den0 = __shfl_sync(0xffffffffu, acc[4][0], l & 28);
        float den1 = __shfl_sync(0xffffffffu, acc[4][2], l & 28);
        if ((l & 3) == 0) {
            sQ[rowbase + (l >> 2)] = 1.f / (den0 + EPSV);
            sQ[rowbase + (l >> 2) + 8] = 1.f / (den1 + EPSV);
        }
    }
    __syncthreads();
    float inv0 = sQ[rowbase + (l >> 2)];
    float inv1 = sQ[rowbase + (l >> 2) + 8];
    const int r0 = rowbase + (l >> 2);
#pragma unroll
    for (int nf = 0; nf < 6; ++nf) {
        int g = 2 * pstart + nf;
        bool own = nh == 0 ? (g <= 4) : (g >= 5 && g <= 7);
        if (!own) continue;
        int c0 = g * 8 + 2 * (l & 3);
#pragma unroll
        for (int hh = 0; hh < 2; ++hh) {
            int row = r0 + hh * 8;
            float inv = hh ? inv1 : inv0;
            size_t base = (size_t)(m0 + row) * 1024 + h * 64 + c0;
#pragma unroll
            for (int cc = 0; cc < 2; ++cc) {
                float yv = acc[nf][hh * 2 + cc] * inv;
                __nv_bfloat16 hv = __float2bfloat16(yv);
                gYh[base + cc] = hv;
                gYl[base + cc] = __float2bfloat16(yv - __bfloat162float(hv));
            }
        }
    }
}

// ============================================================================
// host launch  (order keeps chunk_out_mma in the ncu -s 5 profiled slot)
// ============================================================================
extern "C" void kernel_launch(void* const* d_in, const int* in_sizes, int n_in,
                              void* d_out, int out_size)
{
    const float* hs = (const float*)d_in[0];
    const float* Wq = (const float*)d_in[1];
    const float* Wk = (const float*)d_in[2];
    const float* Wv = (const float*)d_in[3];
    const float* Wo = (const float*)d_in[4];
    float* out = (float*)d_out;

    float* pQKV;
    __nv_bfloat16 *pHh, *pHl, *pWh, *pWl, *pWoh, *pWol, *pYh, *pYl;
    cudaGetSymbolAddress((void**)&pQKV, gQKV);
    cudaGetSymbolAddress((void**)&pHh, gHh);
    cudaGetSymbolAddress((void**)&pHl, gHl);
    cudaGetSymbolAddress((void**)&pWh, gWh);
    cudaGetSymbolAddress((void**)&pWl, gWl);
    cudaGetSymbolAddress((void**)&pWoh, gWoh);
    cudaGetSymbolAddress((void**)&pWol, gWol);
    cudaGetSymbolAddress((void**)&pYh, gYh);
    cudaGetSymbolAddress((void**)&pYl, gYl);

    const int SMEM_G  = 131072;                                       // 2 x 64KB
    const int SMEM_CS = (2 * 288 * LDA_A + 2 * 80 * LDA_A) * 2;       // 200192
    const int SMEM_CO = (2 * 128 * LDA_C + 2 * 80 * LDA_C) * 2
                      + 128 * 17 * 4 + 4 * 128 * LDQK * 2;            // 159744
    cudaFuncSetAttribute(gemm_mma,
                         cudaFuncAttributeMaxDynamicSharedMemorySize, SMEM_G);
    cudaFuncSetAttribute(chunk_state_mma,
                         cudaFuncAttributeMaxDynamicSharedMemorySize, SMEM_CS);
    cudaFuncSetAttribute(chunk_out_mma,
                         cudaFuncAttributeMaxDynamicSharedMemorySize, SMEM_CO);

    // 1-2: conversions
    cvt_hilo<<<8192, 256>>>(hs, pHh, pHl);
    cvt3_w<<<1536, 256>>>(Wq, Wk, Wv, pWh, pWl);
    // 3: fused Q|K|V projection (N = 1536)
    gemm_mma<<<dim3(12, 64), 512, SMEM_G>>>(pHh, pHl, pWh, pWl, pQKV, 1536, 1024);
    // 4-6: chunked linear attention (chunk_out is 6th -> profiled)
    chunk_state_mma<<<1024, 512, SMEM_CS>>>();
    prefix_kernel<<<512, 256>>>();
    chunk_out_mma<<<1024, 512, SMEM_CO>>>();
    // 7-8: output projection
    cvt_hilo<<<1024, 256>>>(Wo, pWoh, pWol);
    gemm_mma<<<dim3(8, 64), 512, SMEM_G>>>(pYh, pYl, pWoh, pWol, out, 1024, 1024);
}

// round 15
// speedup vs baseline: 1.2766x; 1.0922x over previous
#include <cuda_runtime.h>
#include <cuda_bf16.h>
#include <cstdint>

#define DE 273
#define EPSV 1e-12f
#define C2F 0.17677669529663688f  // 1/(4*sqrt(2))

// ----- scratch (static device allocations; no cudaMalloc allowed) -----
__device__ float gQKV[8192 * 1536];        // [m][0:256 Q | 256:512 K | 512:1536 V]
__device__ float gS[1024 * 65 * 288];      // per-chunk S^T|z fp32: [bid][e 0..64][d 0..287]
__device__ __nv_bfloat16 gSh[1024 * 65 * 288];  // exclusive-prefixed, bf16 hi
__device__ __nv_bfloat16 gSl[1024 * 65 * 288];  // exclusive-prefixed, bf16 lo
__device__ __nv_bfloat16 gHh[8192 * 1024];
__device__ __nv_bfloat16 gHl[8192 * 1024];
__device__ __nv_bfloat16 gWh[1536 * 1024];
__device__ __nv_bfloat16 gWl[1536 * 1024];
__device__ __nv_bfloat16 gWoh[1024 * 1024];
__device__ __nv_bfloat16 gWol[1024 * 1024];
__device__ __nv_bfloat16 gYh[8192 * 1024];
__device__ __nv_bfloat16 gYl[8192 * 1024];

// ============================================================================
// helpers (portable PTX only: cp.async / ldmatrix / mma.sync)
// ============================================================================
__device__ __forceinline__ uint32_t smem_u32(const void* p) {
    uint32_t a;
    asm("{ .reg .u64 t; cvta.to.shared.u64 t, %1; cvt.u32.u64 %0, t; }" : "=r"(a) : "l"(p));
    return a;
}
__device__ __forceinline__ void cpasync16(uint32_t dst, const void* src) {
    asm volatile("cp.async.cg.shared.global [%0], [%1], 16;" :: "r"(dst), "l"(src));
}
__device__ __forceinline__ void cpasync_commit() {
    asm volatile("cp.async.commit_group;" ::: "memory");
}
__device__ __forceinline__ void cpasync_wait_all() {
    asm volatile("cp.async.wait_group 0;" ::: "memory");
}
__device__ __forceinline__ void ldsm4(uint32_t* r, uint32_t addr) {
    asm volatile("ldmatrix.sync.aligned.m8n8.x4.shared.b16 {%0,%1,%2,%3}, [%4];"
        : "=r"(r[0]), "=r"(r[1]), "=r"(r[2]), "=r"(r[3]) : "r"(addr));
}
__device__ __forceinline__ void mma_bf16(float* d, const uint32_t* a, const uint32_t* b) {
    asm volatile(
        "mma.sync.aligned.m16n8k16.row.col.f32.bf16.bf16.f32 "
        "{%0,%1,%2,%3}, {%4,%5,%6,%7}, {%8,%9}, {%0,%1,%2,%3};"
        : "+f"(d[0]), "+f"(d[1]), "+f"(d[2]), "+f"(d[3])
        : "r"(a[0]), "r"(a[1]), "r"(a[2]), "r"(a[3]), "r"(b[0]), "r"(b[1]));
}
__device__ __forceinline__ uint32_t sw128(uint32_t bo) { return bo ^ ((bo >> 3) & 0x70); }
__device__ __forceinline__ uint32_t hipack(float x, float y) {
    __nv_bfloat162 h(__float2bfloat16(x), __float2bfloat16(y));
    return *(uint32_t*)&h;
}
__device__ __forceinline__ uint32_t lopack(float x, float y) {
    float xr = x - __bfloat162float(__float2bfloat16(x));
    float yr = y - __bfloat162float(__float2bfloat16(y));
    __nv_bfloat162 h(__float2bfloat16(xr), __float2bfloat16(yr));
    return *(uint32_t*)&h;
}
__device__ __forceinline__ void st_hilo(__nv_bfloat16* ph, __nv_bfloat16* pl, float val) {
    __nv_bfloat16 hv = __float2bfloat16(val);
    *ph = hv;
    *pl = __float2bfloat16(val - __bfloat162float(hv));
}

// ============================================================================
// fp32 -> (hi, lo) bf16 split conversions
// ============================================================================
__device__ __forceinline__ void cvt_body(const float* __restrict__ src,
                                         __nv_bfloat16* __restrict__ hi,
                                         __nv_bfloat16* __restrict__ lo, int i)
{
    float4 v = *(const float4*)(src + i);
    __nv_bfloat16 h0 = __float2bfloat16(v.x), h1 = __float2bfloat16(v.y);
    __nv_bfloat16 h2 = __float2bfloat16(v.z), h3 = __float2bfloat16(v.w);
    __nv_bfloat16 l0 = __float2bfloat16(v.x - __bfloat162float(h0));
    __nv_bfloat16 l1 = __float2bfloat16(v.y - __bfloat162float(h1));
    __nv_bfloat16 l2 = __float2bfloat16(v.z - __bfloat162float(h2));
    __nv_bfloat16 l3 = __float2bfloat16(v.w - __bfloat162float(h3));
    __nv_bfloat162* ph = (__nv_bfloat162*)(hi + i);
    __nv_bfloat162* pl = (__nv_bfloat162*)(lo + i);
    ph[0] = __nv_bfloat162(h0, h1); ph[1] = __nv_bfloat162(h2, h3);
    pl[0] = __nv_bfloat162(l0, l1); pl[1] = __nv_bfloat162(l2, l3);
}

__global__ void __launch_bounds__(256) cvt_hilo(
    const float* __restrict__ src, __nv_bfloat16* __restrict__ hi,
    __nv_bfloat16* __restrict__ lo)
{
    int i = (blockIdx.x * 256 + threadIdx.x) * 4;
    cvt_body(src, hi, lo, i);
}

// Wq (blocks 0..255) | Wk (256..511) | Wv (512..1535) -> contiguous hi/lo
__global__ void __launch_bounds__(256) cvt3_w(
    const float* __restrict__ Wq, const float* __restrict__ Wk,
    const float* __restrict__ Wv, __nv_bfloat16* __restrict__ hi,
    __nv_bfloat16* __restrict__ lo)
{
    int blk = blockIdx.x;
    int i = (blk * 256 + threadIdx.x) * 4;
    const float* src;
    if (blk < 256) src = Wq;
    else if (blk < 512) src = Wk - 256 * 1024;
    else src = Wv - 512 * 1024;
    cvt_body(src, hi, lo, i);
}

// ============================================================================
// split-bf16 HMMA GEMM (NT): C = Ah*Bh + Ah*Bl + Al*Bh, fp32-quality.
// CTA tile 128x128, K stages of 64, 2-stage cp.async, SW128.  512 thr.
// ============================================================================
__global__ void __launch_bounds__(512, 1) gemm_mma(
    const __nv_bfloat16* __restrict__ Ah, const __nv_bfloat16* __restrict__ Al,
    const __nv_bfloat16* __restrict__ Bh, const __nv_bfloat16* __restrict__ Bl,
    float* __restrict__ C, int N, int K)
{
    extern __shared__ char smem[];
    const uint32_t sb = smem_u32(smem);
    const int tid = threadIdx.x, wid = tid >> 5, l = tid & 31;
    const int wm = wid & 3, wn = wid >> 2;
    const int bm = blockIdx.y * 128, bn = blockIdx.x * 128;

    const __nv_bfloat16* gp0[4] = {
        Ah + (size_t)bm * K, Al + (size_t)bm * K,
        Bh + (size_t)bn * K, Bl + (size_t)bn * K };

    const int NST = K >> 6;

    float acc[2][4][4];
#pragma unroll
    for (int mt = 0; mt < 2; ++mt)
#pragma unroll
        for (int nt = 0; nt < 4; ++nt)
#pragma unroll
            for (int c = 0; c < 4; ++c) acc[mt][nt][c] = 0.f;

    {
        const uint32_t sdst = sb;
#pragma unroll
        for (int t = 0; t < 4; ++t)
#pragma unroll
            for (int it = 0; it < 2; ++it) {
                int ch = tid + it * 512;
                int row = ch >> 3, cb = ch & 7;
                cpasync16(sdst + t * 16384 + sw128(row * 128 + cb * 16),
                          gp0[t] + (size_t)row * K + cb * 8);
            }
        cpasync_commit();
    }

    for (int s = 0; s < NST; ++s) {
        cpasync_wait_all();
        __syncthreads();
        if (s + 1 < NST) {
            const uint32_t sdst = sb + (uint32_t)((s + 1) & 1) * 65536u;
            const int k0 = (s + 1) * 64;
#pragma unroll
            for (int t = 0; t < 4; ++t)
#pragma unroll
                for (int it = 0; it < 2; ++it) {
                    int ch = tid + it * 512;
                    int row = ch >> 3, cb = ch & 7;
                    cpasync16(sdst + t * 16384 + sw128(row * 128 + cb * 16),
                              gp0[t] + (size_t)row * K + k0 + cb * 8);
                }
            cpasync_commit();
        }
        const uint32_t sc = sb + (uint32_t)(s & 1) * 65536u;
#pragma unroll
        for (int ks = 0; ks < 4; ++ks) {
            uint32_t ah[2][4], al[2][4];
#pragma unroll
            for (int mt = 0; mt < 2; ++mt) {
                uint32_t bo = (uint32_t)(wm * 32 + mt * 16 + (l & 15)) * 128
                            + ks * 32 + ((l >> 4) << 4);
                bo = sw128(bo);
                ldsm4(ah[mt], sc + bo);
                ldsm4(al[mt], sc + 16384 + bo);
            }
#pragma unroll
            for (int p = 0; p < 2; ++p) {
                uint32_t n = (uint32_t)(wn * 32 + p * 16 + (l & 7) + ((l >> 4) << 3));
                uint32_t bo = n * 128 + ks * 32 + (((l >> 3) & 1) << 4);
                bo = sw128(bo);
                uint32_t rb[4], rl[4];
                ldsm4(rb, sc + 32768 + bo);
                ldsm4(rl, sc + 49152 + bo);
                uint32_t b0[2] = {rb[0], rb[1]}, b1[2] = {rb[2], rb[3]};
                uint32_t c0[2] = {rl[0], rl[1]}, c1[2] = {rl[2], rl[3]};
#pragma unroll
                for (int mt = 0; mt < 2; ++mt) {
                    mma_bf16(acc[mt][2 * p],     ah[mt], b0);
                    mma_bf16(acc[mt][2 * p + 1], ah[mt], b1);
                    mma_bf16(acc[mt][2 * p],     ah[mt], c0);
                    mma_bf16(acc[mt][2 * p + 1], ah[mt], c1);
                    mma_bf16(acc[mt][2 * p],     al[mt], b0);
                    mma_bf16(acc[mt][2 * p + 1], al[mt], b1);
                }
            }
        }
        __syncthreads();
    }

    const int r0 = bm + wm * 32 + (l >> 2);
    const int c0 = bn + wn * 32 + 2 * (l & 3);
#pragma unroll
    for (int mt = 0; mt < 2; ++mt)
#pragma unroll
        for (int nt = 0; nt < 4; ++nt) {
            float* p0 = C + (size_t)(r0 + mt * 16) * N + c0 + nt * 8;
            float* p1 = C + (size_t)(r0 + mt * 16 + 8) * N + c0 + nt * 8;
            *(float2*)p0 = make_float2(acc[mt][nt][0], acc[mt][nt][1]);
            *(float2*)p1 = make_float2(acc[mt][nt][2], acc[mt][nt][3]);
        }
}

// ============================================================================
// Phase A (MMA, 3-pass): per-(bh,c) S_c = kf^T @ v, z via ones-column.
// kf build uses STATIC register indexing: thread qtr owns f1 = 4*qtr + a.
// Writes S^T|z fp32 in [e 0..64][d 0..287] layout (z = row 64).
// ============================================================================
#define LDA_A 136
__global__ void __launch_bounds__(512, 1) chunk_state_mma()
{
    extern __shared__ char smraw[];
    __nv_bfloat16* sKh = (__nv_bfloat16*)smraw;       // 288*136
    __nv_bfloat16* sKl = sKh + 288 * LDA_A;
    __nv_bfloat16* sVh = sKl + 288 * LDA_A;           // 80*136
    __nv_bfloat16* sVl = sVh + 80 * LDA_A;

    const int bid = blockIdx.x;
    const int bh = bid >> 4, c = bid & 15;
    const int b = bh >> 4, h = bh & 15;
    const int tid = threadIdx.x, wid = tid >> 5, l = tid & 31;
    const int wgrp = wid & 7, nh = wid >> 3;
    const int m0 = b * 2048 + c * 128;

    // ---- build kf^T hi/lo with static indexing ----
    {
        const int j = tid >> 2, qtr = tid & 3;
        const float* kp = gQKV + (size_t)(m0 + j) * 1536 + 256 + h * 16;
        float kr[16];
#pragma unroll
        for (int f = 0; f < 16; f += 4) {
            float4 v4 = *(const float4*)(kp + f);
            kr[f] = v4.x; kr[f + 1] = v4.y; kr[f + 2] = v4.z; kr[f + 3] = v4.w;
        }
        float4 kq4 = *(const float4*)(kp + qtr * 4);
        const float kq[4] = {kq4.x * C2F, kq4.y * C2F, kq4.z * C2F, kq4.w * C2F};
        __nv_bfloat16* ph = sKh + j;
        __nv_bfloat16* pl = sKl + j;
        const int dq = 17 + qtr * 64;
#pragma unroll
        for (int a = 0; a < 4; ++a)
#pragma unroll
            for (int f2 = 0; f2 < 16; ++f2) {
                int d = dq + a * 16 + f2;
                st_hilo(ph + d * LDA_A, pl + d * LDA_A, kq[a] * kr[f2]);
            }
        if (qtr == 0) {
            st_hilo(ph, pl, 1.f);
#pragma unroll
            for (int f = 0; f < 16; ++f)
                st_hilo(ph + (1 + f) * LDA_A, pl + (1 + f) * LDA_A, kr[f] * 0.5f);
        } else if (qtr == 3) {
#pragma unroll
            for (int p = 0; p < 15; ++p)
                st_hilo(ph + (273 + p) * LDA_A, pl + (273 + p) * LDA_A, 0.f);
        }
    }
    for (int idx = tid; idx < 8192; idx += 512) {
        int j = idx >> 6, e = idx & 63;
        float v = gQKV[(size_t)(m0 + j) * 1536 + 512 + h * 64 + e];
        st_hilo(sVh + e * LDA_A + j, sVl + e * LDA_A + j, v);
    }
    for (int idx = tid; idx < 16 * 128; idx += 512) {
        int e = 64 + (idx >> 7), j = idx & 127;
        sVh[e * LDA_A + j] = __float2bfloat16(e == 64 ? 1.f : 0.f);
        sVl[e * LDA_A + j] = __float2bfloat16(0.f);
    }
    __syncthreads();

    const uint32_t aKh = smem_u32(sKh), aKl = smem_u32(sKl);
    const uint32_t aVh = smem_u32(sVh), aVl = smem_u32(sVl);
    const int nmf = (wgrp < 2) ? 3 : 2;
    const int pstart = nh * 2;

    float acc[3][6][4];
#pragma unroll
    for (int r = 0; r < 3; ++r)
#pragma unroll
        for (int nf = 0; nf < 6; ++nf)
#pragma unroll
            for (int cc = 0; cc < 4; ++cc) acc[r][nf][cc] = 0.f;

    for (int ks = 0; ks < 8; ++ks) {
        uint32_t ah[3][4], al[3][4];
#pragma unroll
        for (int r = 0; r < 3; ++r) if (r < nmf) {
            int mf = wgrp + 8 * r;
            uint32_t bo = (uint32_t)(mf * 16 + (l & 15)) * (LDA_A * 2)
                        + ks * 32 + ((l >> 4) << 4);
            ldsm4(ah[r], aKh + bo);
            ldsm4(al[r], aKl + bo);
        }
        uint32_t bhf[6][2], blf[6][2];
#pragma unroll
        for (int pp = 0; pp < 3; ++pp) {
            int p = pstart + pp;
            uint32_t n = (uint32_t)(p * 16 + (l & 7) + ((l >> 4) << 3));
            uint32_t bo = n * (LDA_A * 2) + ks * 32 + (((l >> 3) & 1) << 4);
            uint32_t r4[4];
            ldsm4(r4, aVh + bo);
            bhf[2 * pp][0] = r4[0]; bhf[2 * pp][1] = r4[1];
            bhf[2 * pp + 1][0] = r4[2]; bhf[2 * pp + 1][1] = r4[3];
            ldsm4(r4, aVl + bo);
            blf[2 * pp][0] = r4[0]; blf[2 * pp][1] = r4[1];
            blf[2 * pp + 1][0] = r4[2]; blf[2 * pp + 1][1] = r4[3];
        }
#pragma unroll
        for (int r = 0; r < 3; ++r) if (r < nmf)
#pragma unroll
            for (int nf = 0; nf < 6; ++nf) {
                mma_bf16(acc[r][nf], ah[r], bhf[nf]);
                mma_bf16(acc[r][nf], ah[r], blf[nf]);
                mma_bf16(acc[r][nf], al[r], bhf[nf]);
            }
    }

    // ---- writeback S^T|z: outS[e*288 + d] ----
    float* outS = gS + (size_t)bid * (65 * 288);
#pragma unroll
    for (int r = 0; r < 3; ++r) if (r < nmf) {
        int mf = wgrp + 8 * r;
        int d0r = mf * 16 + (l >> 2);
#pragma unroll
        for (int nf = 0; nf < 6; ++nf) {
            int g = 2 * pstart + nf;
            bool own = nh == 0 ? (g <= 4) : (g >= 5 && g <= 8);
            if (!own) continue;
            int c0 = g * 8 + 2 * (l & 3);
#pragma unroll
            for (int hh = 0; hh < 2; ++hh) {
                int d = d0r + hh * 8;
                if (c0 < 64) {
                    outS[(size_t)c0 * 288 + d]       = acc[r][nf][hh * 2];
                    outS[(size_t)(c0 + 1) * 288 + d] = acc[r][nf][hh * 2 + 1];
                } else if (c0 == 64) {
                    outS[(size_t)64 * 288 + d] = acc[r][nf][hh * 2];
                }
            }
        }
    }
}

// ============================================================================
// Phase B: exclusive prefix over 16 chunks per (b,h); emits bf16 hi/lo
// directly in ldsm-ready [e][d] layout.  8 CTAs per bh.
// ============================================================================
__global__ void __launch_bounds__(256) prefix_kernel()
{
    const int bh = blockIdx.x >> 3, part = blockIdx.x & 7;
    const size_t base = (size_t)bh * 16 * (65 * 288);
    const float* Sb = gS + base;
    __nv_bfloat16* Sh = gSh + base;
    __nv_bfloat16* Sl = gSl + base;
    const int i0 = part * 2340, i1 = i0 + 2340;     // 18720/8
    for (int idx = i0 + threadIdx.x; idx < i1; idx += 256) {
        float run = 0.f;
#pragma unroll
        for (int c = 0; c < 16; ++c) {
            size_t off = (size_t)c * (65 * 288) + idx;
            float tmp = Sb[off];
            __nv_bfloat16 hv = __float2bfloat16(run);
            Sh[off] = hv;
            Sl[off] = __float2bfloat16(run - __bfloat162float(hv));
            run += tmp;
        }
    }
}

// ============================================================================
// Phase C (MMA, 3-pass): per-(bh,c) output.  S/z tiles via cp.async; qf build
// with static register indexing (predicated on the 144-wide d-slice).
// ============================================================================
#define LDA_C 152
#define LDQK 24
__global__ void __launch_bounds__(512, 1) chunk_out_mma()
{
    extern __shared__ char smraw[];
    __nv_bfloat16* sAh = (__nv_bfloat16*)smraw;        // 128*152
    __nv_bfloat16* sAl = sAh + 128 * LDA_C;
    __nv_bfloat16* sBh = sAl + 128 * LDA_C;            // 80*152
    __nv_bfloat16* sBl = sBh + 80 * LDA_C;
    float* sQ = (float*)(sBl + 80 * LDA_C);            // 128*17 (reused for den)
    __nv_bfloat16* sQh = (__nv_bfloat16*)(sQ + 128 * 17); // 128*24 each
    __nv_bfloat16* sQl = sQh + 128 * LDQK;
    __nv_bfloat16* sKh = sQl + 128 * LDQK;
    __nv_bfloat16* sKl = sKh + 128 * LDQK;

    const int bid = blockIdx.x;
    const int bh = bid >> 4, c = bid & 15;
    const int b = bh >> 4, h = bh & 15;
    const int tid = threadIdx.x, wid = tid >> 5, l = tid & 31;
    const int wgrp = wid & 7, nh = wid >> 3;
    const int m0 = b * 2048 + c * 128;

    // ---- load q,k; build bf16 hi/lo tiles + fp32 q ----
    for (int idx = tid; idx < 2048; idx += 512) {
        int i = idx >> 4, f = idx & 15;
        float qv = gQKV[(size_t)(m0 + i) * 1536 + h * 16 + f];
        float kv = gQKV[(size_t)(m0 + i) * 1536 + 256 + h * 16 + f];
        sQ[i * 17 + f] = qv;
        st_hilo(sQh + i * LDQK + f, sQl + i * LDQK + f, qv);
        st_hilo(sKh + i * LDQK + f, sKl + i * LDQK + f, kv);
    }
    for (int idx = tid; idx < 8192; idx += 512) {
        int j = idx >> 6, e = idx & 63;
        float v = gQKV[(size_t)(m0 + j) * 1536 + 512 + h * 64 + e];
        st_hilo(sBh + e * LDA_C + j, sBl + e * LDA_C + j, v);
    }
    for (int idx = tid; idx < 16 * 144; idx += 512) {
        int e = 64 + (idx / 144), j = idx % 144;
        sBh[e * LDA_C + j] = __float2bfloat16(e == 64 ? 1.f : 0.f);
        sBl[e * LDA_C + j] = __float2bfloat16(0.f);
    }
    __syncthreads();

    const uint32_t aQh = smem_u32(sQh), aQl = smem_u32(sQl);
    const uint32_t aKh = smem_u32(sKh), aKl = smem_u32(sKl);
    const uint32_t aAh = smem_u32(sAh), aAl = smem_u32(sAl);
    const uint32_t aBh = smem_u32(sBh), aBl = smem_u32(sBl);
    const int pstart = nh * 2;

    // ---- step1: dot MMA (3-pass) + poly/mask + in-register repack ----
    uint32_t ah2[8][4], al2[8][4];
    {
        uint32_t qh4[4], ql4[4];
        uint32_t bo = (uint32_t)(wgrp * 16 + (l & 15)) * (LDQK * 2) + ((l >> 4) << 4);
        ldsm4(qh4, aQh + bo);
        ldsm4(ql4, aQl + bo);
        const int r_lo = wgrp * 16 + (l >> 2);
#pragma unroll
        for (int h2 = 0; h2 < 2; ++h2) {
            float dacc[8][4];
#pragma unroll
            for (int nf = 0; nf < 8; ++nf)
#pragma unroll
                for (int cc = 0; cc < 4; ++cc) dacc[nf][cc] = 0.f;
#pragma unroll
            for (int pp = 0; pp < 4; ++pp) {
                int p = h2 * 4 + pp;
                uint32_t n = (uint32_t)(p * 16 + (l & 7) + ((l >> 4) << 3));
                uint32_t kb = n * (LDQK * 2) + (((l >> 3) & 1) << 4);
                uint32_t rk[4], rkl[4];
                ldsm4(rk, aKh + kb);
                ldsm4(rkl, aKl + kb);
                uint32_t b0[2] = {rk[0], rk[1]}, b1[2] = {rk[2], rk[3]};
                uint32_t c0[2] = {rkl[0], rkl[1]}, c1[2] = {rkl[2], rkl[3]};
                mma_bf16(dacc[2 * pp], qh4, b0);
                mma_bf16(dacc[2 * pp], qh4, c0);
                mma_bf16(dacc[2 * pp], ql4, b0);
                mma_bf16(dacc[2 * pp + 1], qh4, b1);
                mma_bf16(dacc[2 * pp + 1], qh4, c1);
                mma_bf16(dacc[2 * pp + 1], ql4, b1);
            }
#pragma unroll
            for (int nf = 0; nf < 8; ++nf) {
                int colb = (h2 * 8 + nf) * 8 + 2 * (l & 3);
#pragma unroll
                for (int cc = 0; cc < 4; ++cc) {
                    int col = colb + (cc & 1);
                    int row = r_lo + ((cc >> 1) << 3);
                    float dot = dacc[nf][cc];
                    float a = 1.f + dot * 0.25f + dot * dot * 0.03125f;
                    dacc[nf][cc] = (col <= row) ? a : 0.f;
                }
            }
#pragma unroll
            for (int t = 0; t < 4; ++t) {
                int ksg = h2 * 4 + t;
                ah2[ksg][0] = hipack(dacc[2 * t][0], dacc[2 * t][1]);
                ah2[ksg][1] = hipack(dacc[2 * t][2], dacc[2 * t][3]);
                ah2[ksg][2] = hipack(dacc[2 * t + 1][0], dacc[2 * t + 1][1]);
                ah2[ksg][3] = hipack(dacc[2 * t + 1][2], dacc[2 * t + 1][3]);
                al2[ksg][0] = lopack(dacc[2 * t][0], dacc[2 * t][1]);
                al2[ksg][1] = lopack(dacc[2 * t][2], dacc[2 * t][3]);
                al2[ksg][2] = lopack(dacc[2 * t + 1][0], dacc[2 * t + 1][1]);
                al2[ksg][3] = lopack(dacc[2 * t + 1][2], dacc[2 * t + 1][3]);
            }
        }
    }

    float acc[6][4];
#pragma unroll
    for (int nf = 0; nf < 6; ++nf)
#pragma unroll
        for (int cc = 0; cc < 4; ++cc) acc[nf][cc] = 0.f;

    // ---- step2: intra-chunk MMA (attn hi/lo in registers) ----
#pragma unroll
    for (int ks = 0; ks < 8; ++ks) {
        uint32_t bhf[6][2], blf[6][2];
#pragma unroll
        for (int pp = 0; pp < 3; ++pp) {
            int p = pstart + pp;
            uint32_t n = (uint32_t)(p * 16 + (l & 7) + ((l >> 4) << 3));
            uint32_t bo = n * (LDA_C * 2) + ks * 32 + (((l >> 3) & 1) << 4);
            uint32_t r4[4];
            ldsm4(r4, aBh + bo);
            bhf[2 * pp][0] = r4[0]; bhf[2 * pp][1] = r4[1];
            bhf[2 * pp + 1][0] = r4[2]; bhf[2 * pp + 1][1] = r4[3];
            ldsm4(r4, aBl + bo);
            blf[2 * pp][0] = r4[0]; blf[2 * pp][1] = r4[1];
            blf[2 * pp + 1][0] = r4[2]; blf[2 * pp + 1][1] = r4[3];
        }
#pragma unroll
        for (int nf = 0; nf < 6; ++nf) {
            mma_bf16(acc[nf], ah2[ks], bhf[nf]);
            mma_bf16(acc[nf], ah2[ks], blf[nf]);
            mma_bf16(acc[nf], al2[ks], bhf[nf]);
        }
    }
    __syncthreads();

    // ---- step3: inter-chunk, 2 d-tiles of 144; S/z via cp.async ----
    const __nv_bfloat16* Sph = gSh + (size_t)bid * (65 * 288);
    const __nv_bfloat16* Spl = gSl + (size_t)bid * (65 * 288);
#pragma unroll
    for (int dt = 0; dt < 2; ++dt) {
        const int d0 = dt * 144;
        // issue async S/z tile copies (65 rows x 18 chunks of 16B, hi+lo)
        for (int idx = tid; idx < 65 * 18; idx += 512) {
            int e = idx / 18, ch = idx % 18;
            uint32_t so = (uint32_t)(e * LDA_C * 2 + ch * 16);
            const size_t go = (size_t)e * 288 + d0 + ch * 8;
            cpasync16(aBh + so, Sph + go);
            cpasync16(aBl + so, Spl + go);
        }
        cpasync_commit();
        // qf tile (static indexing, overlapped with the copies)
        {
            const int i = tid >> 2, qtr = tid & 3;
            const float* qp = sQ + i * 17;
            float qr[16];
#pragma unroll
            for (int f = 0; f < 16; ++f) qr[f] = qp[f];
            float qq[4];
#pragma unroll
            for (int a = 0; a < 4; ++a) qq[a] = qp[qtr * 4 + a] * C2F;
            __nv_bfloat16* ph = sAh + i * LDA_C;
            __nv_bfloat16* pl = sAl + i * LDA_C;
            const int dq = 17 + qtr * 64;
#pragma unroll
            for (int a = 0; a < 4; ++a)
#pragma unroll
                for (int f2 = 0; f2 < 16; ++f2) {
                    int d = dq + a * 16 + f2;
                    int dloc = d - d0;
                    if (dloc >= 0 && dloc < 144)
                        st_hilo(ph + dloc, pl + dloc, qq[a] * qr[f2]);
                }
            if (dt == 0 && qtr == 0) {
                st_hilo(ph, pl, 1.f);
#pragma unroll
                for (int f = 0; f < 16; ++f)
                    st_hilo(ph + 1 + f, pl + 1 + f, qr[f] * 0.5f);
            }
            if (dt == 1 && qtr == 3) {
#pragma unroll
                for (int p = 0; p < 15; ++p) {
                    ph[129 + p] = __float2bfloat16(0.f);
                    pl[129 + p] = __float2bfloat16(0.f);
                }
            }
        }
        cpasync_wait_all();
        __syncthreads();

        for (int ks = 0; ks < 9; ++ks) {
            uint32_t ah[4], al[4];
            {
                uint32_t bo = (uint32_t)(wgrp * 16 + (l & 15)) * (LDA_C * 2)
                            + ks * 32 + ((l >> 4) << 4);
                ldsm4(ah, aAh + bo);
                ldsm4(al, aAl + bo);
            }
            uint32_t bhf[6][2], blf[6][2];
#pragma unroll
            for (int pp = 0; pp < 3; ++pp) {
                int p = pstart + pp;
                uint32_t n = (uint32_t)(p * 16 + (l & 7) + ((l >> 4) << 3));
                uint32_t bo = n * (LDA_C * 2) + ks * 32 + (((l >> 3) & 1) << 4);
                uint32_t r4[4];
                ldsm4(r4, aBh + bo);
                bhf[2 * pp][0] = r4[0]; bhf[2 * pp][1] = r4[1];
                bhf[2 * pp + 1][0] = r4[2]; bhf[2 * pp + 1][1] = r4[3];
                ldsm4(r4, aBl + bo);
                blf[2 * pp][0] = r4[0]; blf[2 * pp][1] = r4[1];
                blf[2 * pp + 1][0] = r4[2]; blf[2 * pp + 1][1] = r4[3];
            }
#pragma unroll
            for (int nf = 0; nf < 6; ++nf) {
                mma_bf16(acc[nf], ah, bhf[nf]);
                mma_bf16(acc[nf], ah, blf[nf]);
                mma_bf16(acc[nf], al, bhf[nf]);
            }
        }
        __syncthreads();
    }

    // ---- denominator exchange (nh1 owns g=8) then divide + store ----
    const int rowbase = wgrp * 16;
    if (nh == 1) {
        float den0 = __shfl_sync(0xffffffffu, acc[4][0], l & 28);
        float den1 = __shfl_sync(0xffffffffu, acc[4][2], l & 28);
        if ((l & 3) == 0) {
            sQ[rowbase + (l >> 2)] = 1.f / (den0 + EPSV);
            sQ[rowbase + (l >> 2) + 8] = 1.f / (den1 + EPSV);
        }
    }
    __syncthreads();
    float inv0 = sQ[rowbase + (l >> 2)];
    float inv1 = sQ[rowbase + (l >> 2) + 8];
    const int r0 = rowbase + (l >> 2);
#pragma unroll
    for (int nf = 0; nf < 6; ++nf) {
        int g = 2 * pstart + nf;
        bool own = nh == 0 ? (g <= 4) : (g >= 5 && g <= 7);
        if (!own) continue;
        int c0 = g * 8 + 2 * (l & 3);
#pragma unroll
        for (int hh = 0; hh < 2; ++hh) {
            int row = r0 + hh * 8;
            float inv = hh ? inv1 : inv0;
            size_t base = (size_t)(m0 + row) * 1024 + h * 64 + c0;
#pragma unroll
            for (int cc = 0; cc < 2; ++cc) {
                float yv = acc[nf][hh * 2 + cc] * inv;
                __nv_bfloat16 hv = __float2bfloat16(yv);
                gYh[base + cc] = hv;
                gYl[base + cc] = __float2bfloat16(yv - __bfloat162float(hv));
            }
        }
    }
}

// ============================================================================
// host launch  (order keeps attention kernels in the ncu -s 5 profiled slot)
// ============================================================================
extern "C" void kernel_launch(void* const* d_in, const int* in_sizes, int n_in,
                              void* d_out, int out_size)
{
    const float* hs = (const float*)d_in[0];
    const float* Wq = (const float*)d_in[1];
    const float* Wk = (const float*)d_in[2];
    const float* Wv = (const float*)d_in[3];
    const float* Wo = (const float*)d_in[4];
    float* out = (float*)d_out;

    float* pQKV;
    __nv_bfloat16 *pHh, *pHl, *pWh, *pWl, *pWoh, *pWol, *pYh, *pYl;
    cudaGetSymbolAddress((void**)&pQKV, gQKV);
    cudaGetSymbolAddress((void**)&pHh, gHh);
    cudaGetSymbolAddress((void**)&pHl, gHl);
    cudaGetSymbolAddress((void**)&pWh, gWh);
    cudaGetSymbolAddress((void**)&pWl, gWl);
    cudaGetSymbolAddress((void**)&pWoh, gWoh);
    cudaGetSymbolAddress((void**)&pWol, gWol);
    cudaGetSymbolAddress((void**)&pYh, gYh);
    cudaGetSymbolAddress((void**)&pYl, gYl);

    const int SMEM_G  = 131072;                                       // 2 x 64KB
    const int SMEM_CS = (2 * 288 * LDA_A + 2 * 80 * LDA_A) * 2;       // 200192
    const int SMEM_CO = (2 * 128 * LDA_C + 2 * 80 * LDA_C) * 2
                      + 128 * 17 * 4 + 4 * 128 * LDQK * 2;            // 159744
    cudaFuncSetAttribute(gemm_mma,
                         cudaFuncAttributeMaxDynamicSharedMemorySize, SMEM_G);
    cudaFuncSetAttribute(chunk_state_mma,
                         cudaFuncAttributeMaxDynamicSharedMemorySize, SMEM_CS);
    cudaFuncSetAttribute(chunk_out_mma,
                         cudaFuncAttributeMaxDynamicSharedMemorySize, SMEM_CO);

    // 1-2: conversions
    cvt_hilo<<<8192, 256>>>(hs, pHh, pHl);
    cvt3_w<<<1536, 256>>>(Wq, Wk, Wv, pWh, pWl);
    // 3: fused Q|K|V projection (N = 1536)
    gemm_mma<<<dim3(12, 64), 512, SMEM_G>>>(pHh, pHl, pWh, pWl, pQKV, 1536, 1024);
    // 4-6: chunked linear attention
    chunk_state_mma<<<1024, 512, SMEM_CS>>>();
    prefix_kernel<<<512, 256>>>();
    chunk_out_mma<<<1024, 512, SMEM_CO>>>();
    // 7-8: output projection
    cvt_hilo<<<1024, 256>>>(Wo, pWoh, pWol);
    gemm_mma<<<dim3(8, 64), 512, SMEM_G>>>(pYh, pYl, pWoh, pWol, out, 1024, 1024);
}

// round 17
// speedup vs baseline: 1.2875x; 1.0085x over previous
#include <cuda_runtime.h>
#include <cuda_bf16.h>
#include <cstdint>

#define DE 273
#define EPSV 1e-12f
#define C2F 0.17677669529663688f  // 1/(4*sqrt(2))

// ----- scratch (static device allocations; no cudaMalloc allowed) -----
__device__ float gQKV[8192 * 1536];        // [m][0:256 Q | 256:512 K | 512:1536 V]
__device__ float gS[1024 * 65 * 288];      // per-chunk S^T|z fp32: [bid][e 0..64][d 0..287]
__device__ __nv_bfloat16 gSh[1024 * 65 * 288];  // exclusive-prefixed, bf16 hi
__device__ __nv_bfloat16 gSl[1024 * 65 * 288];  // exclusive-prefixed, bf16 lo
__device__ __nv_bfloat16 gHh[8192 * 1024];
__device__ __nv_bfloat16 gHl[8192 * 1024];
__device__ __nv_bfloat16 gWh[1536 * 1024];
__device__ __nv_bfloat16 gWl[1536 * 1024];
__device__ __nv_bfloat16 gWoh[1024 * 1024];
__device__ __nv_bfloat16 gWol[1024 * 1024];
__device__ __nv_bfloat16 gYh[8192 * 1024];
__device__ __nv_bfloat16 gYl[8192 * 1024];

// ============================================================================
// helpers (portable PTX only: cp.async / ldmatrix / mma.sync)
// ============================================================================
__device__ __forceinline__ uint32_t smem_u32(const void* p) {
    uint32_t a;
    asm("{ .reg .u64 t; cvta.to.shared.u64 t, %1; cvt.u32.u64 %0, t; }" : "=r"(a) : "l"(p));
    return a;
}
__device__ __forceinline__ void cpasync16(uint32_t dst, const void* src) {
    asm volatile("cp.async.cg.shared.global [%0], [%1], 16;" :: "r"(dst), "l"(src));
}
__device__ __forceinline__ void cpasync_commit() {
    asm volatile("cp.async.commit_group;" ::: "memory");
}
__device__ __forceinline__ void cpasync_wait_all() {
    asm volatile("cp.async.wait_group 0;" ::: "memory");
}
__device__ __forceinline__ void ldsm4(uint32_t* r, uint32_t addr) {
    asm volatile("ldmatrix.sync.aligned.m8n8.x4.shared.b16 {%0,%1,%2,%3}, [%4];"
        : "=r"(r[0]), "=r"(r[1]), "=r"(r[2]), "=r"(r[3]) : "r"(addr));
}
__device__ __forceinline__ void mma_bf16(float* d, const uint32_t* a, const uint32_t* b) {
    asm volatile(
        "mma.sync.aligned.m16n8k16.row.col.f32.bf16.bf16.f32 "
        "{%0,%1,%2,%3}, {%4,%5,%6,%7}, {%8,%9}, {%0,%1,%2,%3};"
        : "+f"(d[0]), "+f"(d[1]), "+f"(d[2]), "+f"(d[3])
        : "r"(a[0]), "r"(a[1]), "r"(a[2]), "r"(a[3]), "r"(b[0]), "r"(b[1]));
}
__device__ __forceinline__ uint32_t sw128(uint32_t bo) { return bo ^ ((bo >> 3) & 0x70); }

// ---- truncation-based bf16 hi/lo split (no F2FP anywhere) ----
// hi = truncate(f) to bf16 (exact residual), lo = truncate(f - hi).
// |f - hi - lo| <= 2^-16 |f|.
__device__ __forceinline__ uint32_t prmt7632(uint32_t x, uint32_t y) {
    uint32_t r;
    asm("prmt.b32 %0, %1, %2, 0x7632;" : "=r"(r) : "r"(x), "r"(y));
    return r;  // (hi16 of y) : (hi16 of x)
}
__device__ __forceinline__ void st_hilo(__nv_bfloat16* ph, __nv_bfloat16* pl, float val) {
    uint32_t u = __float_as_uint(val);
    float hi = __uint_as_float(u & 0xFFFF0000u);
    *(uint16_t*)ph = (uint16_t)(u >> 16);
    float lo = val - hi;
    *(uint16_t*)pl = (uint16_t)(__float_as_uint(lo) >> 16);
}
// pack (x,y) hi-truncations into one bf16x2 register
__device__ __forceinline__ uint32_t hipack(float x, float y) {
    return prmt7632(__float_as_uint(x), __float_as_uint(y));
}
// pack (x,y) lo-residual truncations
__device__ __forceinline__ uint32_t lopack(float x, float y) {
    float xh = __uint_as_float(__float_as_uint(x) & 0xFFFF0000u);
    float yh = __uint_as_float(__float_as_uint(y) & 0xFFFF0000u);
    return prmt7632(__float_as_uint(x - xh), __float_as_uint(y - yh));
}

// ============================================================================
// fp32 -> (hi, lo) bf16 split conversions (truncation split, PRMT-packed)
// ============================================================================
__device__ __forceinline__ void cvt_body(const float* __restrict__ src,
                                         __nv_bfloat16* __restrict__ hi,
                                         __nv_bfloat16* __restrict__ lo, int i)
{
    float4 v = *(const float4*)(src + i);
    uint32_t* ph = (uint32_t*)(hi + i);
    uint32_t* pl = (uint32_t*)(lo + i);
    ph[0] = hipack(v.x, v.y);
    ph[1] = hipack(v.z, v.w);
    pl[0] = lopack(v.x, v.y);
    pl[1] = lopack(v.z, v.w);
}

__global__ void __launch_bounds__(256) cvt_hilo(
    const float* __restrict__ src, __nv_bfloat16* __restrict__ hi,
    __nv_bfloat16* __restrict__ lo)
{
    int i = (blockIdx.x * 256 + threadIdx.x) * 4;
    cvt_body(src, hi, lo, i);
}

// Wq (blocks 0..255) | Wk (256..511) | Wv (512..1535) -> contiguous hi/lo
__global__ void __launch_bounds__(256) cvt3_w(
    const float* __restrict__ Wq, const float* __restrict__ Wk,
    const float* __restrict__ Wv, __nv_bfloat16* __restrict__ hi,
    __nv_bfloat16* __restrict__ lo)
{
    int blk = blockIdx.x;
    int i = (blk * 256 + threadIdx.x) * 4;
    const float* src;
    if (blk < 256) src = Wq;
    else if (blk < 512) src = Wk - 256 * 1024;
    else src = Wv - 512 * 1024;
    cvt_body(src, hi, lo, i);
}

// ============================================================================
// split-bf16 HMMA GEMM (NT): C = Ah*Bh + Ah*Bl + Al*Bh, fp32-quality.
// CTA tile 128x128, K stages of 64, 2-stage cp.async, SW128.  512 thr.
// ============================================================================
__global__ void __launch_bounds__(512, 1) gemm_mma(
    const __nv_bfloat16* __restrict__ Ah, const __nv_bfloat16* __restrict__ Al,
    const __nv_bfloat16* __restrict__ Bh, const __nv_bfloat16* __restrict__ Bl,
    float* __restrict__ C, int N, int K)
{
    extern __shared__ char smem[];
    const uint32_t sb = smem_u32(smem);
    const int tid = threadIdx.x, wid = tid >> 5, l = tid & 31;
    const int wm = wid & 3, wn = wid >> 2;
    const int bm = blockIdx.y * 128, bn = blockIdx.x * 128;

    const __nv_bfloat16* gp0[4] = {
        Ah + (size_t)bm * K, Al + (size_t)bm * K,
        Bh + (size_t)bn * K, Bl + (size_t)bn * K };

    const int NST = K >> 6;

    float acc[2][4][4];
#pragma unroll
    for (int mt = 0; mt < 2; ++mt)
#pragma unroll
        for (int nt = 0; nt < 4; ++nt)
#pragma unroll
            for (int c = 0; c < 4; ++c) acc[mt][nt][c] = 0.f;

    {
        const uint32_t sdst = sb;
#pragma unroll
        for (int t = 0; t < 4; ++t)
#pragma unroll
            for (int it = 0; it < 2; ++it) {
                int ch = tid + it * 512;
                int row = ch >> 3, cb = ch & 7;
                cpasync16(sdst + t * 16384 + sw128(row * 128 + cb * 16),
                          gp0[t] + (size_t)row * K + cb * 8);
            }
        cpasync_commit();
    }

    for (int s = 0; s < NST; ++s) {
        cpasync_wait_all();
        __syncthreads();
        if (s + 1 < NST) {
            const uint32_t sdst = sb + (uint32_t)((s + 1) & 1) * 65536u;
            const int k0 = (s + 1) * 64;
#pragma unroll
            for (int t = 0; t < 4; ++t)
#pragma unroll
                for (int it = 0; it < 2; ++it) {
                    int ch = tid + it * 512;
                    int row = ch >> 3, cb = ch & 7;
                    cpasync16(sdst + t * 16384 + sw128(row * 128 + cb * 16),
                              gp0[t] + (size_t)row * K + k0 + cb * 8);
                }
            cpasync_commit();
        }
        const uint32_t sc = sb + (uint32_t)(s & 1) * 65536u;
#pragma unroll
        for (int ks = 0; ks < 4; ++ks) {
            uint32_t ah[2][4], al[2][4];
#pragma unroll
            for (int mt = 0; mt < 2; ++mt) {
                uint32_t bo = (uint32_t)(wm * 32 + mt * 16 + (l & 15)) * 128
                            + ks * 32 + ((l >> 4) << 4);
                bo = sw128(bo);
                ldsm4(ah[mt], sc + bo);
                ldsm4(al[mt], sc + 16384 + bo);
            }
#pragma unroll
            for (int p = 0; p < 2; ++p) {
                uint32_t n = (uint32_t)(wn * 32 + p * 16 + (l & 7) + ((l >> 4) << 3));
                uint32_t bo = n * 128 + ks * 32 + (((l >> 3) & 1) << 4);
                bo = sw128(bo);
                uint32_t rb[4], rl[4];
                ldsm4(rb, sc + 32768 + bo);
                ldsm4(rl, sc + 49152 + bo);
                uint32_t b0[2] = {rb[0], rb[1]}, b1[2] = {rb[2], rb[3]};
                uint32_t c0[2] = {rl[0], rl[1]}, c1[2] = {rl[2], rl[3]};
#pragma unroll
                for (int mt = 0; mt < 2; ++mt) {
                    mma_bf16(acc[mt][2 * p],     ah[mt], b0);
                    mma_bf16(acc[mt][2 * p + 1], ah[mt], b1);
                    mma_bf16(acc[mt][2 * p],     ah[mt], c0);
                    mma_bf16(acc[mt][2 * p + 1], ah[mt], c1);
                    mma_bf16(acc[mt][2 * p],     al[mt], b0);
                    mma_bf16(acc[mt][2 * p + 1], al[mt], b1);
                }
            }
        }
        __syncthreads();
    }

    const int r0 = bm + wm * 32 + (l >> 2);
    const int c0 = bn + wn * 32 + 2 * (l & 3);
#pragma unroll
    for (int mt = 0; mt < 2; ++mt)
#pragma unroll
        for (int nt = 0; nt < 4; ++nt) {
            float* p0 = C + (size_t)(r0 + mt * 16) * N + c0 + nt * 8;
            float* p1 = C + (size_t)(r0 + mt * 16 + 8) * N + c0 + nt * 8;
            *(float2*)p0 = make_float2(acc[mt][nt][0], acc[mt][nt][1]);
            *(float2*)p1 = make_float2(acc[mt][nt][2], acc[mt][nt][3]);
        }
}

// ============================================================================
// Phase A (MMA, 3-pass): per-(bh,c) S_c = kf^T @ v, z via ones-column.
// kf build: static register indexing + truncation split (ALU only).
// Writes S^T|z fp32 in [e 0..64][d 0..287] layout (z = row 64).
// ============================================================================
#define LDA_A 136
__global__ void __launch_bounds__(512, 1) chunk_state_mma()
{
    extern __shared__ char smraw[];
    __nv_bfloat16* sKh = (__nv_bfloat16*)smraw;       // 288*136
    __nv_bfloat16* sKl = sKh + 288 * LDA_A;
    __nv_bfloat16* sVh = sKl + 288 * LDA_A;           // 80*136
    __nv_bfloat16* sVl = sVh + 80 * LDA_A;

    const int bid = blockIdx.x;
    const int bh = bid >> 4, c = bid & 15;
    const int b = bh >> 4, h = bh & 15;
    const int tid = threadIdx.x, wid = tid >> 5, l = tid & 31;
    const int wgrp = wid & 7, nh = wid >> 3;
    const int m0 = b * 2048 + c * 128;

    // ---- build kf^T hi/lo with static indexing ----
    {
        const int j = tid >> 2, qtr = tid & 3;
        const float* kp = gQKV + (size_t)(m0 + j) * 1536 + 256 + h * 16;
        float kr[16];
#pragma unroll
        for (int f = 0; f < 16; f += 4) {
            float4 v4 = *(const float4*)(kp + f);
            kr[f] = v4.x; kr[f + 1] = v4.y; kr[f + 2] = v4.z; kr[f + 3] = v4.w;
        }
        float4 kq4 = *(const float4*)(kp + qtr * 4);
        const float kq[4] = {kq4.x * C2F, kq4.y * C2F, kq4.z * C2F, kq4.w * C2F};
        __nv_bfloat16* ph = sKh + j;
        __nv_bfloat16* pl = sKl + j;
        const int dq = 17 + qtr * 64;
#pragma unroll
        for (int a = 0; a < 4; ++a)
#pragma unroll
            for (int f2 = 0; f2 < 16; ++f2) {
                int d = dq + a * 16 + f2;
                st_hilo(ph + d * LDA_A, pl + d * LDA_A, kq[a] * kr[f2]);
            }
        if (qtr == 0) {
            st_hilo(ph, pl, 1.f);
#pragma unroll
            for (int f = 0; f < 16; ++f)
                st_hilo(ph + (1 + f) * LDA_A, pl + (1 + f) * LDA_A, kr[f] * 0.5f);
        } else if (qtr == 3) {
#pragma unroll
            for (int p = 0; p < 15; ++p)
                st_hilo(ph + (273 + p) * LDA_A, pl + (273 + p) * LDA_A, 0.f);
        }
    }
    for (int idx = tid; idx < 8192; idx += 512) {
        int j = idx >> 6, e = idx & 63;
        float v = gQKV[(size_t)(m0 + j) * 1536 + 512 + h * 64 + e];
        st_hilo(sVh + e * LDA_A + j, sVl + e * LDA_A + j, v);
    }
    for (int idx = tid; idx < 16 * 128; idx += 512) {
        int e = 64 + (idx >> 7), j = idx & 127;
        sVh[e * LDA_A + j] = __float2bfloat16(e == 64 ? 1.f : 0.f);
        sVl[e * LDA_A + j] = __float2bfloat16(0.f);
    }
    __syncthreads();

    const uint32_t aKh = smem_u32(sKh), aKl = smem_u32(sKl);
    const uint32_t aVh = smem_u32(sVh), aVl = smem_u32(sVl);
    const int nmf = (wgrp < 2) ? 3 : 2;
    const int pstart = nh * 2;

    float acc[3][6][4];
#pragma unroll
    for (int r = 0; r < 3; ++r)
#pragma unroll
        for (int nf = 0; nf < 6; ++nf)
#pragma unroll
            for (int cc = 0; cc < 4; ++cc) acc[r][nf][cc] = 0.f;

    for (int ks = 0; ks < 8; ++ks) {
        uint32_t ah[3][4], al[3][4];
#pragma unroll
        for (int r = 0; r < 3; ++r) if (r < nmf) {
            int mf = wgrp + 8 * r;
            uint32_t bo = (uint32_t)(mf * 16 + (l & 15)) * (LDA_A * 2)
                        + ks * 32 + ((l >> 4) << 4);
            ldsm4(ah[r], aKh + bo);
            ldsm4(al[r], aKl + bo);
        }
        uint32_t bhf[6][2], blf[6][2];
#pragma unroll
        for (int pp = 0; pp < 3; ++pp) {
            int p = pstart + pp;
            uint32_t n = (uint32_t)(p * 16 + (l & 7) + ((l >> 4) << 3));
            uint32_t bo = n * (LDA_A * 2) + ks * 32 + (((l >> 3) & 1) << 4);
            uint32_t r4[4];
            ldsm4(r4, aVh + bo);
            bhf[2 * pp][0] = r4[0]; bhf[2 * pp][1] = r4[1];
            bhf[2 * pp + 1][0] = r4[2]; bhf[2 * pp + 1][1] = r4[3];
            ldsm4(r4, aVl + bo);
            blf[2 * pp][0] = r4[0]; blf[2 * pp][1] = r4[1];
            blf[2 * pp + 1][0] = r4[2]; blf[2 * pp + 1][1] = r4[3];
        }
#pragma unroll
        for (int r = 0; r < 3; ++r) if (r < nmf)
#pragma unroll
            for (int nf = 0; nf < 6; ++nf) {
                mma_bf16(acc[r][nf], ah[r], bhf[nf]);
                mma_bf16(acc[r][nf], ah[r], blf[nf]);
                mma_bf16(acc[r][nf], al[r], bhf[nf]);
            }
    }

    // ---- writeback S^T|z: outS[e*288 + d] ----
    float* outS = gS + (size_t)bid * (65 * 288);
#pragma unroll
    for (int r = 0; r < 3; ++r) if (r < nmf) {
        int mf = wgrp + 8 * r;
        int d0r = mf * 16 + (l >> 2);
#pragma unroll
        for (int nf = 0; nf < 6; ++nf) {
            int g = 2 * pstart + nf;
            bool own = nh == 0 ? (g <= 4) : (g >= 5 && g <= 8);
            if (!own) continue;
            int c0 = g * 8 + 2 * (l & 3);
#pragma unroll
            for (int hh = 0; hh < 2; ++hh) {
                int d = d0r + hh * 8;
                if (c0 < 64) {
                    outS[(size_t)c0 * 288 + d]       = acc[r][nf][hh * 2];
                    outS[(size_t)(c0 + 1) * 288 + d] = acc[r][nf][hh * 2 + 1];
                } else if (c0 == 64) {
                    outS[(size_t)64 * 288 + d] = acc[r][nf][hh * 2];
                }
            }
        }
    }
}

// ============================================================================
// Phase B: exclusive prefix over 16 chunks per (b,h); emits bf16 hi/lo
// (truncation split) in ldsm-ready [e][d] layout.  8 CTAs per bh.
// ============================================================================
__global__ void __launch_bounds__(256) prefix_kernel()
{
    const int bh = blockIdx.x >> 3, part = blockIdx.x & 7;
    const size_t base = (size_t)bh * 16 * (65 * 288);
    const float* Sb = gS + base;
    __nv_bfloat16* Sh = gSh + base;
    __nv_bfloat16* Sl = gSl + base;
    const int i0 = part * 2340, i1 = i0 + 2340;     // 18720/8
    for (int idx = i0 + threadIdx.x; idx < i1; idx += 256) {
        float run = 0.f;
#pragma unroll
        for (int c = 0; c < 16; ++c) {
            size_t off = (size_t)c * (65 * 288) + idx;
            float tmp = Sb[off];
            st_hilo(Sh + off, Sl + off, run);
            run += tmp;
        }
    }
}

// ============================================================================
// Phase C (MMA, 3-pass): per-(bh,c) output.  S/z tiles via cp.async; qf build
// static-indexed; repack uses PRMT truncation packs.
// ============================================================================
#define LDA_C 152
#define LDQK 24
__global__ void __launch_bounds__(512, 1) chunk_out_mma()
{
    extern __shared__ char smraw[];
    __nv_bfloat16* sAh = (__nv_bfloat16*)smraw;        // 128*152
    __nv_bfloat16* sAl = sAh + 128 * LDA_C;
    __nv_bfloat16* sBh = sAl + 128 * LDA_C;            // 80*152
    __nv_bfloat16* sBl = sBh + 80 * LDA_C;
    float* sQ = (float*)(sBl + 80 * LDA_C);            // 128*17 (reused for den)
    __nv_bfloat16* sQh = (__nv_bfloat16*)(sQ + 128 * 17); // 128*24 each
    __nv_bfloat16* sQl = sQh + 128 * LDQK;
    __nv_bfloat16* sKh = sQl + 128 * LDQK;
    __nv_bfloat16* sKl = sKh + 128 * LDQK;

    const int bid = blockIdx.x;
    const int bh = bid >> 4, c = bid & 15;
    const int b = bh >> 4, h = bh & 15;
    const int tid = threadIdx.x, wid = tid >> 5, l = tid & 31;
    const int wgrp = wid & 7, nh = wid >> 3;
    const int m0 = b * 2048 + c * 128;

    // ---- load q,k; build bf16 hi/lo tiles + fp32 q ----
    for (int idx = tid; idx < 2048; idx += 512) {
        int i = idx >> 4, f = idx & 15;
        float qv = gQKV[(size_t)(m0 + i) * 1536 + h * 16 + f];
        float kv = gQKV[(size_t)(m0 + i) * 1536 + 256 + h * 16 + f];
        sQ[i * 17 + f] = qv;
        st_hilo(sQh + i * LDQK + f, sQl + i * LDQK + f, qv);
        st_hilo(sKh + i * LDQK + f, sKl + i * LDQK + f, kv);
    }
    for (int idx = tid; idx < 8192; idx += 512) {
        int j = idx >> 6, e = idx & 63;
        float v = gQKV[(size_t)(m0 + j) * 1536 + 512 + h * 64 + e];
        st_hilo(sBh + e * LDA_C + j, sBl + e * LDA_C + j, v);
    }
    for (int idx = tid; idx < 16 * 144; idx += 512) {
        int e = 64 + (idx / 144), j = idx % 144;
        sBh[e * LDA_C + j] = __float2bfloat16(e == 64 ? 1.f : 0.f);
        sBl[e * LDA_C + j] = __float2bfloat16(0.f);
    }
    __syncthreads();

    const uint32_t aQh = smem_u32(sQh), aQl = smem_u32(sQl);
    const uint32_t aKh = smem_u32(sKh), aKl = smem_u32(sKl);
    const uint32_t aAh = smem_u32(sAh), aAl = smem_u32(sAl);
    const uint32_t aBh = smem_u32(sBh), aBl = smem_u32(sBl);
    const int pstart = nh * 2;

    // ---- step1: dot MMA (3-pass) + poly/mask + in-register repack ----
    uint32_t ah2[8][4], al2[8][4];
    {
        uint32_t qh4[4], ql4[4];
        uint32_t bo = (uint32_t)(wgrp * 16 + (l & 15)) * (LDQK * 2) + ((l >> 4) << 4);
        ldsm4(qh4, aQh + bo);
        ldsm4(ql4, aQl + bo);
        const int r_lo = wgrp * 16 + (l >> 2);
#pragma unroll
        for (int h2 = 0; h2 < 2; ++h2) {
            float dacc[8][4];
#pragma unroll
            for (int nf = 0; nf < 8; ++nf)
#pragma unroll
                for (int cc = 0; cc < 4; ++cc) dacc[nf][cc] = 0.f;
#pragma unroll
            for (int pp = 0; pp < 4; ++pp) {
                int p = h2 * 4 + pp;
                uint32_t n = (uint32_t)(p * 16 + (l & 7) + ((l >> 4) << 3));
                uint32_t kb = n * (LDQK * 2) + (((l >> 3) & 1) << 4);
                uint32_t rk[4], rkl[4];
                ldsm4(rk, aKh + kb);
                ldsm4(rkl, aKl + kb);
                uint32_t b0[2] = {rk[0], rk[1]}, b1[2] = {rk[2], rk[3]};
                uint32_t c0[2] = {rkl[0], rkl[1]}, c1[2] = {rkl[2], rkl[3]};
                mma_bf16(dacc[2 * pp], qh4, b0);
                mma_bf16(dacc[2 * pp], qh4, c0);
                mma_bf16(dacc[2 * pp], ql4, b0);
                mma_bf16(dacc[2 * pp + 1], qh4, b1);
                mma_bf16(dacc[2 * pp + 1], qh4, c1);
                mma_bf16(dacc[2 * pp + 1], ql4, b1);
            }
#pragma unroll
            for (int nf = 0; nf < 8; ++nf) {
                int colb = (h2 * 8 + nf) * 8 + 2 * (l & 3);
#pragma unroll
                for (int cc = 0; cc < 4; ++cc) {
                    int col = colb + (cc & 1);
                    int row = r_lo + ((cc >> 1) << 3);
                    float dot = dacc[nf][cc];
                    float a = 1.f + dot * 0.25f + dot * dot * 0.03125f;
                    dacc[nf][cc] = (col <= row) ? a : 0.f;
                }
            }
#pragma unroll
            for (int t = 0; t < 4; ++t) {
                int ksg = h2 * 4 + t;
                ah2[ksg][0] = hipack(dacc[2 * t][0], dacc[2 * t][1]);
                ah2[ksg][1] = hipack(dacc[2 * t][2], dacc[2 * t][3]);
                ah2[ksg][2] = hipack(dacc[2 * t + 1][0], dacc[2 * t + 1][1]);
                ah2[ksg][3] = hipack(dacc[2 * t + 1][2], dacc[2 * t + 1][3]);
                al2[ksg][0] = lopack(dacc[2 * t][0], dacc[2 * t][1]);
                al2[ksg][1] = lopack(dacc[2 * t][2], dacc[2 * t][3]);
                al2[ksg][2] = lopack(dacc[2 * t + 1][0], dacc[2 * t + 1][1]);
                al2[ksg][3] = lopack(dacc[2 * t + 1][2], dacc[2 * t + 1][3]);
            }
        }
    }

    float acc[6][4];
#pragma unroll
    for (int nf = 0; nf < 6; ++nf)
#pragma unroll
        for (int cc = 0; cc < 4; ++cc) acc[nf][cc] = 0.f;

    // ---- step2: intra-chunk MMA (attn hi/lo in registers) ----
#pragma unroll
    for (int ks = 0; ks < 8; ++ks) {
        uint32_t bhf[6][2], blf[6][2];
#pragma unroll
        for (int pp = 0; pp < 3; ++pp) {
            int p = pstart + pp;
            uint32_t n = (uint32_t)(p * 16 + (l & 7) + ((l >> 4) << 3));
            uint32_t bo = n * (LDA_C * 2) + ks * 32 + (((l >> 3) & 1) << 4);
            uint32_t r4[4];
            ldsm4(r4, aBh + bo);
            bhf[2 * pp][0] = r4[0]; bhf[2 * pp][1] = r4[1];
            bhf[2 * pp + 1][0] = r4[2]; bhf[2 * pp + 1][1] = r4[3];
            ldsm4(r4, aBl + bo);
            blf[2 * pp][0] = r4[0]; blf[2 * pp][1] = r4[1];
            blf[2 * pp + 1][0] = r4[2]; blf[2 * pp + 1][1] = r4[3];
        }
#pragma unroll
        for (int nf = 0; nf < 6; ++nf) {
            mma_bf16(acc[nf], ah2[ks], bhf[nf]);
            mma_bf16(acc[nf], ah2[ks], blf[nf]);
            mma_bf16(acc[nf], al2[ks], bhf[nf]);
        }
    }
    __syncthreads();

    // ---- step3: inter-chunk, 2 d-tiles of 144; S/z via cp.async ----
    const __nv_bfloat16* Sph = gSh + (size_t)bid * (65 * 288);
    const __nv_bfloat16* Spl = gSl + (size_t)bid * (65 * 288);
#pragma unroll
    for (int dt = 0; dt < 2; ++dt) {
        const int d0 = dt * 144;
        // issue async S/z tile copies (65 rows x 18 chunks of 16B, hi+lo)
        for (int idx = tid; idx < 65 * 18; idx += 512) {
            int e = idx / 18, ch = idx % 18;
            uint32_t so = (uint32_t)(e * LDA_C * 2 + ch * 16);
            const size_t go = (size_t)e * 288 + d0 + ch * 8;
            cpasync16(aBh + so, Sph + go);
            cpasync16(aBl + so, Spl + go);
        }
        cpasync_commit();
        // qf tile (static indexing, overlapped with the copies)
        {
            const int i = tid >> 2, qtr = tid & 3;
            const float* qp = sQ + i * 17;
            float qr[16];
#pragma unroll
            for (int f = 0; f < 16; ++f) qr[f] = qp[f];
            float qq[4];
#pragma unroll
            for (int a = 0; a < 4; ++a) qq[a] = qp[qtr * 4 + a] * C2F;
            __nv_bfloat16* ph = sAh + i * LDA_C;
            __nv_bfloat16* pl = sAl + i * LDA_C;
            const int dq = 17 + qtr * 64;
#pragma unroll
            for (int a = 0; a < 4; ++a)
#pragma unroll
                for (int f2 = 0; f2 < 16; ++f2) {
                    int d = dq + a * 16 + f2;
                    int dloc = d - d0;
                    if (dloc >= 0 && dloc < 144)
                        st_hilo(ph + dloc, pl + dloc, qq[a] * qr[f2]);
                }
            if (dt == 0 && qtr == 0) {
                st_hilo(ph, pl, 1.f);
#pragma unroll
                for (int f = 0; f < 16; ++f)
                    st_hilo(ph + 1 + f, pl + 1 + f, qr[f] * 0.5f);
            }
            if (dt == 1 && qtr == 3) {
#pragma unroll
                for (int p = 0; p < 15; ++p) {
                    ph[129 + p] = __float2bfloat16(0.f);
                    pl[129 + p] = __float2bfloat16(0.f);
                }
            }
        }
        cpasync_wait_all();
        __syncthreads();

        for (int ks = 0; ks < 9; ++ks) {
            uint32_t ah[4], al[4];
            {
                uint32_t bo = (uint32_t)(wgrp * 16 + (l & 15)) * (LDA_C * 2)
                            + ks * 32 + ((l >> 4) << 4);
                ldsm4(ah, aAh + bo);
                ldsm4(al, aAl + bo);
            }
            uint32_t bhf[6][2], blf[6][2];
#pragma unroll
            for (int pp = 0; pp < 3; ++pp) {
                int p = pstart + pp;
                uint32_t n = (uint32_t)(p * 16 + (l & 7) + ((l >> 4) << 3));
                uint32_t bo = n * (LDA_C * 2) + ks * 32 + (((l >> 3) & 1) << 4);
                uint32_t r4[4];
                ldsm4(r4, aBh + bo);
                bhf[2 * pp][0] = r4[0]; bhf[2 * pp][1] = r4[1];
                bhf[2 * pp + 1][0] = r4[2]; bhf[2 * pp + 1][1] = r4[3];
                ldsm4(r4, aBl + bo);
                blf[2 * pp][0] = r4[0]; blf[2 * pp][1] = r4[1];
                blf[2 * pp + 1][0] = r4[2]; blf[2 * pp + 1][1] = r4[3];
            }
#pragma unroll
            for (int nf = 0; nf < 6; ++nf) {
                mma_bf16(acc[nf], ah, bhf[nf]);
                mma_bf16(acc[nf], ah, blf[nf]);
                mma_bf16(acc[nf], al, bhf[nf]);
            }
        }
        __syncthreads();
    }

    // ---- denominator exchange (nh1 owns g=8) then divide + store ----
    const int rowbase = wgrp * 16;
    if (nh == 1) {
        float den0 = __shfl_sync(0xffffffffu, acc[4][0], l & 28);
        float den1 = __shfl_sync(0xffffffffu, acc[4][2], l & 28);
        if ((l & 3) == 0) {
            sQ[rowbase + (l >> 2)] = 1.f / (den0 + EPSV);
            sQ[rowbase + (l >> 2) + 8] = 1.f / (den1 + EPSV);
        }
    }
    __syncthreads();
    float inv0 = sQ[rowbase + (l >> 2)];
    float inv1 = sQ[rowbase + (l >> 2) + 8];
    const int r0 = rowbase + (l >> 2);
#pragma unroll
    for (int nf = 0; nf < 6; ++nf) {
        int g = 2 * pstart + nf;
        bool own = nh == 0 ? (g <= 4) : (g >= 5 && g <= 7);
        if (!own) continue;
        int c0 = g * 8 + 2 * (l & 3);
#pragma unroll
        for (int hh = 0; hh < 2; ++hh) {
            int row = r0 + hh * 8;
            float inv = hh ? inv1 : inv0;
            size_t base = (size_t)(m0 + row) * 1024 + h * 64 + c0;
#pragma unroll
            for (int cc = 0; cc < 2; ++cc) {
                float yv = acc[nf][hh * 2 + cc] * inv;
                st_hilo(gYh + base + cc, gYl + base + cc, yv);
            }
        }
    }
}

// ============================================================================
// host launch  (order keeps attention kernels in the ncu -s 5 profiled slot)
// ============================================================================
extern "C" void kernel_launch(void* const* d_in, const int* in_sizes, int n_in,
                              void* d_out, int out_size)
{
    const float* hs = (const float*)d_in[0];
    const float* Wq = (const float*)d_in[1];
    const float* Wk = (const float*)d_in[2];
    const float* Wv = (const float*)d_in[3];
    const float* Wo = (const float*)d_in[4];
    float* out = (float*)d_out;

    float* pQKV;
    __nv_bfloat16 *pHh, *pHl, *pWh, *pWl, *pWoh, *pWol, *pYh, *pYl;
    cudaGetSymbolAddress((void**)&pQKV, gQKV);
    cudaGetSymbolAddress((void**)&pHh, gHh);
    cudaGetSymbolAddress((void**)&pHl, gHl);
    cudaGetSymbolAddress((void**)&pWh, gWh);
    cudaGetSymbolAddress((void**)&pWl, gWl);
    cudaGetSymbolAddress((void**)&pWoh, gWoh);
    cudaGetSymbolAddress((void**)&pWol, gWol);
    cudaGetSymbolAddress((void**)&pYh, gYh);
    cudaGetSymbolAddress((void**)&pYl, gYl);

    const int SMEM_G  = 131072;                                       // 2 x 64KB
    const int SMEM_CS = (2 * 288 * LDA_A + 2 * 80 * LDA_A) * 2;       // 200192
    const int SMEM_CO = (2 * 128 * LDA_C + 2 * 80 * LDA_C) * 2
                      + 128 * 17 * 4 + 4 * 128 * LDQK * 2;            // 159744
    cudaFuncSetAttribute(gemm_mma,
                         cudaFuncAttributeMaxDynamicSharedMemorySize, SMEM_G);
    cudaFuncSetAttribute(chunk_state_mma,
                         cudaFuncAttributeMaxDynamicSharedMemorySize, SMEM_CS);
    cudaFuncSetAttribute(chunk_out_mma,
                         cudaFuncAttributeMaxDynamicSharedMemorySize, SMEM_CO);

    // 1-2: conversions
    cvt_hilo<<<8192, 256>>>(hs, pHh, pHl);
    cvt3_w<<<1536, 256>>>(Wq, Wk, Wv, pWh, pWl);
    // 3: fused Q|K|V projection (N = 1536)
    gemm_mma<<<dim3(12, 64), 512, SMEM_G>>>(pHh, pHl, pWh, pWl, pQKV, 1536, 1024);
    // 4-6: chunked linear attention
    chunk_state_mma<<<1024, 512, SMEM_CS>>>();
    prefix_kernel<<<512, 256>>>();
    chunk_out_mma<<<1024, 512, SMEM_CO>>>();
    // 7-8: output projection
    cvt_hilo<<<1024, 256>>>(Wo, pWoh, pWol);
    gemm_mma<<<dim3(8, 64), 512, SMEM_G>>>(pYh, pYl, pWoh, pWol, out, 1024, 1024);
}